// round 6
// baseline (speedup 1.0000x reference)
#include <cuda_runtime.h>

#define SEQ 192
#define NH 8

__device__ float g_xn[SEQ * 512];
__device__ float g_proj[SEQ * 2560];
__device__ float g_bsum[SEQ * 64];
__device__ float g_wkr[4096 * 512];
__device__ float g_step1[SEQ * 4096];
__device__ float g_step2[SEQ * SEQ * 64];
__device__ float g_dT[NH * 64 * SEQ];
__device__ float g_Epre[NH * SEQ * 64];
__device__ float g_F[NH * SEQ * SEQ * 64];
__device__ float g_Z[NH * SEQ];
__device__ float g_U[NH * SEQ * 4096];
__device__ float g_zbuf[SEQ * 512];

typedef unsigned long long u64t;

__device__ __forceinline__ u64t pk2(float lo, float hi) {
    u64t d; asm("mov.b64 %0, {%1, %2};" : "=l"(d) : "f"(lo), "f"(hi)); return d;
}
__device__ __forceinline__ float2 upk2(u64t d) {
    float2 r; asm("mov.b64 {%0, %1}, %2;" : "=f"(r.x), "=f"(r.y) : "l"(d)); return r;
}
__device__ __forceinline__ u64t ffma2(u64t a, u64t b, u64t c) {
    u64t d; asm("fma.rn.f32x2 %0, %1, %2, %3;" : "=l"(d) : "l"(a), "l"(b), "l"(c)); return d;
}

__device__ __forceinline__ float fexp(float x) {
    float t = fmaf(x, 1.4426950408889634f, 12582912.0f);
    float kf = t - 12582912.0f;
    int ki = (int)kf;
    float r = fmaf(kf, -0.69314718055994531f, x);
    float p = 1.38888889e-3f;
    p = fmaf(p, r, 8.33333333e-3f);
    p = fmaf(p, r, 4.16666667e-2f);
    p = fmaf(p, r, 1.66666667e-1f);
    p = fmaf(p, r, 0.5f);
    p = fmaf(p, r, 1.0f);
    p = fmaf(p, r, 1.0f);
    return p * __int_as_float((ki + 127) << 23);
}

__global__ __launch_bounds__(256) void ln_kernel(const float* __restrict__ x,
                                                 const float* __restrict__ w,
                                                 const float* __restrict__ b,
                                                 float* __restrict__ xn) {
    __shared__ float rs[256], rq[256];
    int row = blockIdx.x, tid = threadIdx.x;
    float v0 = x[row * 512 + tid], v1 = x[row * 512 + 256 + tid];
    rs[tid] = v0 + v1;
    rq[tid] = v0 * v0 + v1 * v1;
    __syncthreads();
    for (int s = 128; s >= 32; s >>= 1) {
        if (tid < s) { rs[tid] += rs[tid + s]; rq[tid] += rq[tid + s]; }
        __syncthreads();
    }
    if (tid < 32) {
        float a = rs[tid], q = rq[tid];
        for (int o = 16; o; o >>= 1) {
            a += __shfl_down_sync(~0u, a, o);
            q += __shfl_down_sync(~0u, q, o);
        }
        if (!tid) { rs[0] = a; rq[0] = q; }
    }
    __syncthreads();
    float mu = rs[0] * (1.f / 512.f);
    float var = rq[0] * (1.f / 512.f) - mu * mu;
    float is = rsqrtf(var + 1e-5f);
    xn[row * 512 + tid]       = (v0 - mu) * is * w[tid]       + b[tid];
    xn[row * 512 + 256 + tid] = (v1 - mu) * is * w[256 + tid] + b[256 + tid];
}

// 64x64 tile GEMM, 256 threads (8 warps -> 2 warps/SMSP), thread tile 4m x 4n,
// register-prefetch double buffering.
__global__ __launch_bounds__(256) void gemm_kernel(
    const float* __restrict__ A, int lda, long sA1, long sA2,
    const float* __restrict__ B, int ldbn, int ldbk, long sB1, long sB2,
    float* __restrict__ C, int ldc, long sC1, long sC2,
    const float* __restrict__ bias,
    int K, int nb1, int kSplits, int doAtomic)
{
    __shared__ float Ast[16][68];
    __shared__ float Bst[16][68];
    int z = blockIdx.z;
    int kz = z % kSplits;
    int t = z / kSplits;
    int b1 = t % nb1, b2 = t / nb1;
    A += b1 * sA1 + b2 * sA2;
    B += b1 * sB1 + b2 * sB2;
    C += b1 * sC1 + b2 * sC2;
    const int kPer = K / kSplits;
    const int k0 = kz * kPer, k1 = k0 + kPer;
    const int m0 = blockIdx.y * 64;
    const int n0 = blockIdx.x * 64;
    const int tid = threadIdx.x;
    const int tn0 = (tid & 15) * 4;
    const int tm0 = (tid >> 4) * 4;
    const int lm = tid >> 2, lk = (tid & 3) * 4;

    u64t acc[2][4];
#pragma unroll
    for (int i = 0; i < 2; i++)
#pragma unroll
        for (int j = 0; j < 4; j++) acc[i][j] = 0ULL;

    float4 pa, pb;
    float pbs[4];

    pa = *(const float4*)(A + (long)(m0 + lm) * lda + k0 + lk);
    if (ldbk == 1) {
        pb = *(const float4*)(B + (long)(n0 + lm) * ldbn + k0 + lk);
    } else {
#pragma unroll
        for (int j = 0; j < 4; j++) {
            int idx = tid + j * 256;
            pbs[j] = B[(long)(k0 + (idx >> 6)) * ldbk + (long)(n0 + (idx & 63)) * ldbn];
        }
    }

    for (int kk = k0; kk < k1; kk += 16) {
        Ast[lk + 0][lm] = pa.x; Ast[lk + 1][lm] = pa.y;
        Ast[lk + 2][lm] = pa.z; Ast[lk + 3][lm] = pa.w;
        if (ldbk == 1) {
            Bst[lk + 0][lm] = pb.x; Bst[lk + 1][lm] = pb.y;
            Bst[lk + 2][lm] = pb.z; Bst[lk + 3][lm] = pb.w;
        } else {
#pragma unroll
            for (int j = 0; j < 4; j++) {
                int idx = tid + j * 256;
                Bst[idx >> 6][idx & 63] = pbs[j];
            }
        }
        __syncthreads();

        if (kk + 16 < k1) {
            int kn = kk + 16;
            pa = *(const float4*)(A + (long)(m0 + lm) * lda + kn + lk);
            if (ldbk == 1) {
                pb = *(const float4*)(B + (long)(n0 + lm) * ldbn + kn + lk);
            } else {
#pragma unroll
                for (int j = 0; j < 4; j++) {
                    int idx = tid + j * 256;
                    pbs[j] = B[(long)(kn + (idx >> 6)) * ldbk + (long)(n0 + (idx & 63)) * ldbn];
                }
            }
        }

#pragma unroll
        for (int k = 0; k < 16; k++) {
            ulonglong2 a01 = *(const ulonglong2*)&Ast[k][tm0];
            float4 bv = *(const float4*)&Bst[k][tn0];
            u64t b0 = pk2(bv.x, bv.x), b1p = pk2(bv.y, bv.y);
            u64t b2p = pk2(bv.z, bv.z), b3p = pk2(bv.w, bv.w);
            acc[0][0] = ffma2(a01.x, b0, acc[0][0]);
            acc[0][1] = ffma2(a01.x, b1p, acc[0][1]);
            acc[0][2] = ffma2(a01.x, b2p, acc[0][2]);
            acc[0][3] = ffma2(a01.x, b3p, acc[0][3]);
            acc[1][0] = ffma2(a01.y, b0, acc[1][0]);
            acc[1][1] = ffma2(a01.y, b1p, acc[1][1]);
            acc[1][2] = ffma2(a01.y, b2p, acc[1][2]);
            acc[1][3] = ffma2(a01.y, b3p, acc[1][3]);
        }
        __syncthreads();
    }
#pragma unroll
    for (int mp = 0; mp < 2; mp++)
#pragma unroll
        for (int j = 0; j < 4; j++) {
            float2 v = upk2(acc[mp][j]);
            int m = m0 + tm0 + mp * 2;
            int nn = n0 + tn0 + j;
            if (doAtomic) {
                atomicAdd(&C[(long)m * ldc + nn], v.x);
                atomicAdd(&C[(long)(m + 1) * ldc + nn], v.y);
            } else {
                float bb = bias ? bias[nn] : 0.f;
                C[(long)m * ldc + nn] = v.x + bb;
                C[(long)(m + 1) * ldc + nn] = v.y + bb;
            }
        }
}

__global__ void bsum_kernel(const float* __restrict__ proj, float* __restrict__ bs) {
    int idx = blockIdx.x * 256 + threadIdx.x;
    if (idx < SEQ * 64) {
        int q = idx >> 6, j = idx & 63;
        float s = 0.f;
#pragma unroll
        for (int nn = 0; nn < 8; nn++) s += proj[q * 2560 + 512 + nn * 64 + j];
        bs[idx] = s;
    }
}

__global__ void reshape_wk(const float* __restrict__ wk, float* __restrict__ out) {
    for (int o = blockIdx.x * blockDim.x + threadIdx.x; o < 4096 * 512;
         o += gridDim.x * blockDim.x) {
        int ij = o >> 9, nk = o & 511;
        int n = nk >> 6, k = nk & 63;
        int i = ij >> 6, j = ij & 63;
        out[o] = wk[n * 262144 + i * 4096 + j * 64 + k];
    }
}

__global__ void dT_kernel(const float* __restrict__ proj, float* __restrict__ dT) {
    int idx = blockIdx.x * 256 + threadIdx.x;
    if (idx < NH * 64 * SEQ) {
        int n = idx / (64 * SEQ);
        int rem = idx - n * 64 * SEQ;
        int h = rem / SEQ, p = rem % SEQ;
        dT[idx] = proj[p * 2560 + 1536 + n * 64 + h];
    }
}

__global__ void epre_kernel(const float* __restrict__ proj, float* __restrict__ Epre) {
    int n = blockIdx.x, g = threadIdx.x;
    float run = 0.f;
    for (int p0 = 0; p0 < SEQ; p0 += 8) {
        float v[8];
#pragma unroll
        for (int j = 0; j < 8; j++)
            v[j] = proj[(p0 + j) * 2560 + 2048 + n * 64 + g];
#pragma unroll
        for (int j = 0; j < 8; j++) {
            run += v[j];
            Epre[((long)n * SEQ + p0 + j) * 64 + g] = run;
        }
    }
}

__global__ void zero_kernel(float* p, int n) {
    int i = blockIdx.x * 256 + threadIdx.x;
    if (i < n) p[i] = 0.f;
}

__global__ void fillb_kernel(float* __restrict__ C, const float* __restrict__ bias, int n) {
    int i = blockIdx.x * 256 + threadIdx.x;
    if (i < n) C[i] = bias[i & 511];
}

__global__ void zscale_kernel(float* __restrict__ zb, const float* __restrict__ Z) {
    int idx = blockIdx.x * 256 + threadIdx.x;
    if (idx < SEQ * 512) {
        int r = idx >> 9, c = idx & 511;
        int n = c >> 6;
        zb[idx] = zb[idx] / Z[n * SEQ + r];
    }
}

__global__ __launch_bounds__(192, 2) void attn_kernel(
    const float* __restrict__ proj, const float* __restrict__ step2,
    const float* __restrict__ Epre,
    float* __restrict__ F, float* __restrict__ Z)
{
    extern __shared__ float sm[];
    float* St = sm;
    float* Es = sm + 12288;
    __shared__ float zred[8];
    int r = blockIdx.x, n = blockIdx.y, p = threadIdx.x;

    {
        const float4* src = (const float4*)(step2 + (long)r * 12288);
        for (int i = p; i < 3072; i += 192) ((float4*)St)[i] = src[i];
        for (int i = p; i < 3072; i += 192) {
            int q = i >> 4, g4 = i & 15;
            ((float4*)Es)[i] = *(const float4*)(proj + q * 2560 + 2048 + n * 64 + g4 * 4);
        }
    }
    u64t a2[32];
#pragma unroll
    for (int i = 0; i < 32; i++)
        a2[i] = *(const u64t*)(proj + p * 2560 + n * 64 + 2 * i);
    __syncthreads();

    u64t F2[32];
    {
        const u64t* Ep = (const u64t*)(Epre + ((long)n * SEQ + p) * 64);
#pragma unroll
        for (int j = 0; j < 32; j++) F2[j] = Ep[j];
    }
    float Zacc = (float)(p + 1);

    for (int q = 0; q < 192; q++) {
        if (q > p) {
            const ulonglong2* Stp = (const ulonglong2*)&St[q * 64];
            u64t sA = 0ULL, sB = 0ULL;
#pragma unroll
            for (int j = 0; j < 16; j++) {
                ulonglong2 sv = Stp[j];
                sA = ffma2(a2[2 * j], sv.x, sA);
                sB = ffma2(a2[2 * j + 1], sv.y, sB);
            }
            float2 fa = upk2(sA), fb = upk2(sB);
            float ex = fexp((fa.x + fa.y + fb.x + fb.y) * 0.015625f);
            Zacc += ex;
            u64t exd = pk2(ex, ex);
            const ulonglong2* Ep2 = (const ulonglong2*)&Es[q * 64];
#pragma unroll
            for (int j2 = 0; j2 < 16; j2++) {
                ulonglong2 ev = Ep2[j2];
                F2[2 * j2]     = ffma2(exd, ev.x, F2[2 * j2]);
                F2[2 * j2 + 1] = ffma2(exd, ev.y, F2[2 * j2 + 1]);
            }
        }
    }

    u64t* Fp = (u64t*)(F + (((long)(n * SEQ + r)) * SEQ + p) * 64);
#pragma unroll
    for (int j = 0; j < 32; j++) Fp[j] = F2[j];

    float zw = Zacc;
    for (int o = 16; o; o >>= 1) zw += __shfl_down_sync(~0u, zw, o);
    if ((p & 31) == 0) zred[p >> 5] = zw;
    __syncthreads();
    if (p == 0) {
        float zt = 0.f;
        for (int w = 0; w < 6; w++) zt += zred[w];
        Z[n * SEQ + r] = zt;
    }
}

extern "C" void kernel_launch(void* const* d_in, const int* in_sizes, int n_in,
                              void* d_out, int out_size) {
    const float* x       = (const float*)d_in[0];
    const float* ln_w    = (const float*)d_in[1];
    const float* ln_b    = (const float*)d_in[2];
    const float* W_abcde = (const float*)d_in[3];
    const float* b_abcde = (const float*)d_in[4];
    const float* W_K     = (const float*)d_in[5];
    const float* W_V     = (const float*)d_in[6];
    const float* W_out   = (const float*)d_in[7];
    const float* b_out   = (const float*)d_in[8];
    float* out = (float*)d_out;

    float *xn, *proj, *bsum, *wkr, *step1, *step2, *dT, *Epre, *F, *Z, *U, *zb;
    cudaGetSymbolAddress((void**)&xn, g_xn);
    cudaGetSymbolAddress((void**)&proj, g_proj);
    cudaGetSymbolAddress((void**)&bsum, g_bsum);
    cudaGetSymbolAddress((void**)&wkr, g_wkr);
    cudaGetSymbolAddress((void**)&step1, g_step1);
    cudaGetSymbolAddress((void**)&step2, g_step2);
    cudaGetSymbolAddress((void**)&dT, g_dT);
    cudaGetSymbolAddress((void**)&Epre, g_Epre);
    cudaGetSymbolAddress((void**)&F, g_F);
    cudaGetSymbolAddress((void**)&Z, g_Z);
    cudaGetSymbolAddress((void**)&U, g_U);
    cudaGetSymbolAddress((void**)&zb, g_zbuf);

    cudaFuncSetAttribute(attn_kernel, cudaFuncAttributeMaxDynamicSharedMemorySize, 98304);

    // 1
    ln_kernel<<<SEQ, 256>>>(x, ln_w, ln_b, xn);
    // 2
    reshape_wk<<<2048, 256>>>(W_K, wkr);
    // 3: proj
    gemm_kernel<<<dim3(40, 3, 1), 256>>>(xn, 512, 0, 0, W_abcde, 512, 1, 0, 0,
                                         proj, 2560, 0, 0, b_abcde, 512, 1, 1, 0);
    // 4: step1  <-- ncu profiled slot
    gemm_kernel<<<dim3(64, 3, 1), 256>>>(proj + 1024, 2560, 0, 0, wkr, 512, 1, 0, 0,
                                         step1, 4096, 0, 0, 0, 512, 1, 1, 0);
    // 5
    bsum_kernel<<<48, 256>>>(proj, bsum);
    // 6
    dT_kernel<<<(NH * 64 * SEQ + 255) / 256, 256>>>(proj, dT);
    // 7
    epre_kernel<<<NH, 64>>>(proj, Epre);
    // 8: step2
    gemm_kernel<<<dim3(1, 3, 192), 256>>>(bsum, 64, 0, 0, step1, 64, 1, 4096, 0,
                                          step2, 64, 12288, 0, 0, 64, 192, 1, 0);
    // 9: attn
    attn_kernel<<<dim3(192, 8), 192, 98304>>>(proj, step2, Epre, F, Z);
    // 10: U
    gemm_kernel<<<dim3(1, 1, 1536), 256>>>(dT, 192, 0, 12288,
                                           F, 1, 64, 12288, 2359296,
                                           U, 64, 4096, 786432, 0, 192, 192, 1, 0);
    // 11-13: z
    zero_kernel<<<(SEQ * 512 + 255) / 256, 256>>>(zb, SEQ * 512);
    gemm_kernel<<<dim3(1, 3, 64), 256>>>(U, 4096, 786432, 0,
                                         W_V, 1, 64, 262144, 0,
                                         zb, 512, 64, 0, 0, 4096, 8, 8, 1);
    zscale_kernel<<<(SEQ * 512 + 255) / 256, 256>>>(zb, Z);
    // 14-15: out
    fillb_kernel<<<(SEQ * 512 + 255) / 256, 256>>>(out, b_out, SEQ * 512);
    gemm_kernel<<<dim3(8, 3, 4), 256>>>(zb, 512, 0, 0, W_out, 512, 1, 0, 0,
                                        out, 512, 0, 0, 0, 512, 1, 4, 1);
}

// round 8
// speedup vs baseline: 1.0715x; 1.0715x over previous
#include <cuda_runtime.h>

#define SEQ 192
#define NH 8

__device__ float g_xn[SEQ * 512];
__device__ float g_proj[SEQ * 2560];
__device__ float g_bsum[SEQ * 64];
__device__ float g_wkr[4096 * 512];
__device__ float g_step1[SEQ * 4096];
__device__ float g_step2[SEQ * SEQ * 64];
__device__ float g_dT[NH * 64 * SEQ];
__device__ float g_Epre[NH * SEQ * 64];
__device__ float g_F[NH * SEQ * SEQ * 64];
__device__ float g_Z[NH * SEQ];
__device__ float g_U[NH * SEQ * 4096];
__device__ float g_zbuf[SEQ * 512];

typedef unsigned long long u64t;

__device__ __forceinline__ u64t pk2(float lo, float hi) {
    u64t d; asm("mov.b64 %0, {%1, %2};" : "=l"(d) : "f"(lo), "f"(hi)); return d;
}
__device__ __forceinline__ float2 upk2(u64t d) {
    float2 r; asm("mov.b64 {%0, %1}, %2;" : "=f"(r.x), "=f"(r.y) : "l"(d)); return r;
}
__device__ __forceinline__ u64t ffma2(u64t a, u64t b, u64t c) {
    u64t d; asm("fma.rn.f32x2 %0, %1, %2, %3;" : "=l"(d) : "l"(a), "l"(b), "l"(c)); return d;
}
__device__ __forceinline__ u64t add2(u64t a, u64t b) {
    u64t d; asm("add.rn.f32x2 %0, %1, %2;" : "=l"(d) : "l"(a), "l"(b)); return d;
}

__device__ __forceinline__ float fexp(float x) {
    float t = fmaf(x, 1.4426950408889634f, 12582912.0f);
    float kf = t - 12582912.0f;
    int ki = (int)kf;
    float r = fmaf(kf, -0.69314718055994531f, x);
    float p = 1.38888889e-3f;
    p = fmaf(p, r, 8.33333333e-3f);
    p = fmaf(p, r, 4.16666667e-2f);
    p = fmaf(p, r, 1.66666667e-1f);
    p = fmaf(p, r, 0.5f);
    p = fmaf(p, r, 1.0f);
    p = fmaf(p, r, 1.0f);
    return p * __int_as_float((ki + 127) << 23);
}

__global__ __launch_bounds__(256) void ln_kernel(const float* __restrict__ x,
                                                 const float* __restrict__ w,
                                                 const float* __restrict__ b,
                                                 float* __restrict__ xn) {
    __shared__ float rs[256], rq[256];
    int row = blockIdx.x, tid = threadIdx.x;
    float v0 = x[row * 512 + tid], v1 = x[row * 512 + 256 + tid];
    rs[tid] = v0 + v1;
    rq[tid] = v0 * v0 + v1 * v1;
    __syncthreads();
    for (int s = 128; s >= 32; s >>= 1) {
        if (tid < s) { rs[tid] += rs[tid + s]; rq[tid] += rq[tid + s]; }
        __syncthreads();
    }
    if (tid < 32) {
        float a = rs[tid], q = rq[tid];
        for (int o = 16; o; o >>= 1) {
            a += __shfl_down_sync(~0u, a, o);
            q += __shfl_down_sync(~0u, q, o);
        }
        if (!tid) { rs[0] = a; rq[0] = q; }
    }
    __syncthreads();
    float mu = rs[0] * (1.f / 512.f);
    float var = rq[0] * (1.f / 512.f) - mu * mu;
    float is = rsqrtf(var + 1e-5f);
    xn[row * 512 + tid]       = (v0 - mu) * is * w[tid]       + b[tid];
    xn[row * 512 + 256 + tid] = (v1 - mu) * is * w[256 + tid] + b[256 + tid];
}

// 64x64 tile GEMM, 128 threads, thread tile 8m x 4n, reg-prefetch double buffer.
__global__ __launch_bounds__(128) void gemm_kernel(
    const float* __restrict__ A, int lda, long sA1, long sA2,
    const float* __restrict__ B, int ldbn, int ldbk, long sB1, long sB2,
    float* __restrict__ C, int ldc, long sC1, long sC2,
    const float* __restrict__ bias,
    int K, int nb1, int kSplits, int doAtomic)
{
    __shared__ float Ast[16][68];
    __shared__ float Bst[16][68];
    int z = blockIdx.z;
    int kz = z % kSplits;
    int t = z / kSplits;
    int b1 = t % nb1, b2 = t / nb1;
    A += b1 * sA1 + b2 * sA2;
    B += b1 * sB1 + b2 * sB2;
    C += b1 * sC1 + b2 * sC2;
    const int kPer = K / kSplits;
    const int k0 = kz * kPer, k1 = k0 + kPer;
    const int m0 = blockIdx.y * 64;
    const int n0 = blockIdx.x * 64;
    const int tid = threadIdx.x;
    const int tn0 = (tid & 15) * 4;
    const int tm0 = (tid >> 4) * 8;
    const int pbn = tid & 63;

    u64t acc[4][4];
#pragma unroll
    for (int i = 0; i < 4; i++)
#pragma unroll
        for (int j = 0; j < 4; j++) acc[i][j] = 0ULL;

    float4 pa[2], pb[2];
    float pbs[8];

#pragma unroll
    for (int j = 0; j < 2; j++) {
        int idx = tid + j * 128;
        pa[j] = *(const float4*)(A + (long)(m0 + (idx >> 2)) * lda + k0 + (idx & 3) * 4);
    }
    if (ldbk == 1) {
#pragma unroll
        for (int j = 0; j < 2; j++) {
            int idx = tid + j * 128;
            pb[j] = *(const float4*)(B + (long)(n0 + (idx >> 2)) * ldbn + k0 + (idx & 3) * 4);
        }
    } else {
#pragma unroll
        for (int j = 0; j < 8; j++) {
            int k = (tid + j * 128) >> 6;
            pbs[j] = B[(long)(k0 + k) * ldbk + (long)(n0 + pbn) * ldbn];
        }
    }

    for (int kk = k0; kk < k1; kk += 16) {
#pragma unroll
        for (int j = 0; j < 2; j++) {
            int idx = tid + j * 128;
            int m = idx >> 2, kq = (idx & 3) * 4;
            Ast[kq + 0][m] = pa[j].x; Ast[kq + 1][m] = pa[j].y;
            Ast[kq + 2][m] = pa[j].z; Ast[kq + 3][m] = pa[j].w;
        }
        if (ldbk == 1) {
#pragma unroll
            for (int j = 0; j < 2; j++) {
                int idx = tid + j * 128;
                int nn = idx >> 2, kq = (idx & 3) * 4;
                Bst[kq + 0][nn] = pb[j].x; Bst[kq + 1][nn] = pb[j].y;
                Bst[kq + 2][nn] = pb[j].z; Bst[kq + 3][nn] = pb[j].w;
            }
        } else {
#pragma unroll
            for (int j = 0; j < 8; j++) {
                int idx = tid + j * 128;
                Bst[idx >> 6][idx & 63] = pbs[j];
            }
        }
        __syncthreads();

        if (kk + 16 < k1) {
            int kn = kk + 16;
#pragma unroll
            for (int j = 0; j < 2; j++) {
                int idx = tid + j * 128;
                pa[j] = *(const float4*)(A + (long)(m0 + (idx >> 2)) * lda + kn + (idx & 3) * 4);
            }
            if (ldbk == 1) {
#pragma unroll
                for (int j = 0; j < 2; j++) {
                    int idx = tid + j * 128;
                    pb[j] = *(const float4*)(B + (long)(n0 + (idx >> 2)) * ldbn + kn + (idx & 3) * 4);
                }
            } else {
#pragma unroll
                for (int j = 0; j < 8; j++) {
                    int k = (tid + j * 128) >> 6;
                    pbs[j] = B[(long)(kn + k) * ldbk + (long)(n0 + pbn) * ldbn];
                }
            }
        }

#pragma unroll
        for (int k = 0; k < 16; k++) {
            ulonglong2 a01 = *(const ulonglong2*)&Ast[k][tm0];
            ulonglong2 a23 = *(const ulonglong2*)&Ast[k][tm0 + 4];
            float4 bv = *(const float4*)&Bst[k][tn0];
            u64t b0 = pk2(bv.x, bv.x), b1p = pk2(bv.y, bv.y);
            u64t b2p = pk2(bv.z, bv.z), b3p = pk2(bv.w, bv.w);
            acc[0][0] = ffma2(a01.x, b0, acc[0][0]);
            acc[0][1] = ffma2(a01.x, b1p, acc[0][1]);
            acc[0][2] = ffma2(a01.x, b2p, acc[0][2]);
            acc[0][3] = ffma2(a01.x, b3p, acc[0][3]);
            acc[1][0] = ffma2(a01.y, b0, acc[1][0]);
            acc[1][1] = ffma2(a01.y, b1p, acc[1][1]);
            acc[1][2] = ffma2(a01.y, b2p, acc[1][2]);
            acc[1][3] = ffma2(a01.y, b3p, acc[1][3]);
            acc[2][0] = ffma2(a23.x, b0, acc[2][0]);
            acc[2][1] = ffma2(a23.x, b1p, acc[2][1]);
            acc[2][2] = ffma2(a23.x, b2p, acc[2][2]);
            acc[2][3] = ffma2(a23.x, b3p, acc[2][3]);
            acc[3][0] = ffma2(a23.y, b0, acc[3][0]);
            acc[3][1] = ffma2(a23.y, b1p, acc[3][1]);
            acc[3][2] = ffma2(a23.y, b2p, acc[3][2]);
            acc[3][3] = ffma2(a23.y, b3p, acc[3][3]);
        }
        __syncthreads();
    }
#pragma unroll
    for (int mp = 0; mp < 4; mp++)
#pragma unroll
        for (int j = 0; j < 4; j++) {
            float2 v = upk2(acc[mp][j]);
            int m = m0 + tm0 + mp * 2;
            int nn = n0 + tn0 + j;
            if (doAtomic) {
                atomicAdd(&C[(long)m * ldc + nn], v.x);
                atomicAdd(&C[(long)(m + 1) * ldc + nn], v.y);
            } else {
                float bb = bias ? bias[nn] : 0.f;
                C[(long)m * ldc + nn] = v.x + bb;
                C[(long)(m + 1) * ldc + nn] = v.y + bb;
            }
        }
}

__global__ void bsum_kernel(const float* __restrict__ proj, float* __restrict__ bs) {
    int idx = blockIdx.x * 256 + threadIdx.x;
    if (idx < SEQ * 64) {
        int q = idx >> 6, j = idx & 63;
        float s = 0.f;
#pragma unroll
        for (int nn = 0; nn < 8; nn++) s += proj[q * 2560 + 512 + nn * 64 + j];
        bs[idx] = s;
    }
}

__global__ void reshape_wk(const float* __restrict__ wk, float* __restrict__ out) {
    for (int o = blockIdx.x * blockDim.x + threadIdx.x; o < 4096 * 512;
         o += gridDim.x * blockDim.x) {
        int ij = o >> 9, nk = o & 511;
        int n = nk >> 6, k = nk & 63;
        int i = ij >> 6, j = ij & 63;
        out[o] = wk[n * 262144 + i * 4096 + j * 64 + k];
    }
}

__global__ void dT_kernel(const float* __restrict__ proj, float* __restrict__ dT) {
    int idx = blockIdx.x * 256 + threadIdx.x;
    if (idx < NH * 64 * SEQ) {
        int n = idx / (64 * SEQ);
        int rem = idx - n * 64 * SEQ;
        int h = rem / SEQ, p = rem % SEQ;
        dT[idx] = proj[p * 2560 + 1536 + n * 64 + h];
    }
}

__global__ void epre_kernel(const float* __restrict__ proj, float* __restrict__ Epre) {
    int n = blockIdx.x, g = threadIdx.x;
    float run = 0.f;
    for (int p0 = 0; p0 < SEQ; p0 += 8) {
        float v[8];
#pragma unroll
        for (int j = 0; j < 8; j++)
            v[j] = proj[(p0 + j) * 2560 + 2048 + n * 64 + g];
#pragma unroll
        for (int j = 0; j < 8; j++) {
            run += v[j];
            Epre[((long)n * SEQ + p0 + j) * 64 + g] = run;
        }
    }
}

__global__ void zero_kernel(float* p, int n) {
    int i = blockIdx.x * 256 + threadIdx.x;
    if (i < n) p[i] = 0.f;
}

__global__ void fillb_kernel(float* __restrict__ C, const float* __restrict__ bias,
                             int n, int ldm) {
    int i = blockIdx.x * 256 + threadIdx.x;
    if (i < n) C[i] = bias[i % ldm];
}

__global__ void zscale_kernel(float* __restrict__ zb, const float* __restrict__ Z) {
    int idx = blockIdx.x * 256 + threadIdx.x;
    if (idx < SEQ * 512) {
        int r = idx >> 9, c = idx & 511;
        int n = c >> 6;
        zb[idx] = zb[idx] / Z[n * SEQ + r];
    }
}

__global__ __launch_bounds__(192, 2) void attn_kernel(
    const float* __restrict__ proj, const float* __restrict__ step2,
    const float* __restrict__ Epre,
    float* __restrict__ F, float* __restrict__ Z)
{
    extern __shared__ float sm[];
    float* St = sm;
    float* Es = sm + 12288;
    __shared__ float zred[8];
    int r = blockIdx.x, n = blockIdx.y, p = threadIdx.x;

    {
        const float4* src = (const float4*)(step2 + (long)r * 12288);
        for (int i = p; i < 3072; i += 192) ((float4*)St)[i] = src[i];
        for (int i = p; i < 3072; i += 192) {
            int q = i >> 4, g4 = i & 15;
            ((float4*)Es)[i] = *(const float4*)(proj + q * 2560 + 2048 + n * 64 + g4 * 4);
        }
    }
    u64t a2[32];
#pragma unroll
    for (int i = 0; i < 32; i++)
        a2[i] = *(const u64t*)(proj + p * 2560 + n * 64 + 2 * i);
    __syncthreads();

    u64t F2[32];
    {
        const u64t* Ep = (const u64t*)(Epre + ((long)n * SEQ + p) * 64);
#pragma unroll
        for (int j = 0; j < 32; j++) F2[j] = Ep[j];
    }
    float Zacc = (float)(p + 1);

    // warp-uniform start: q <= (p & ~31) is masked for every lane in this warp
    for (int q = (p & ~31) + 1; q < 192; q++) {
        if (q > p) {
            const ulonglong2* Stp = (const ulonglong2*)&St[q * 64];
            u64t s0 = 0ULL, s1 = 0ULL, s2 = 0ULL, s3 = 0ULL;
#pragma unroll
            for (int j = 0; j < 8; j++) {
                ulonglong2 v1 = Stp[2 * j];
                ulonglong2 v2 = Stp[2 * j + 1];
                s0 = ffma2(a2[4 * j],     v1.x, s0);
                s1 = ffma2(a2[4 * j + 1], v1.y, s1);
                s2 = ffma2(a2[4 * j + 2], v2.x, s2);
                s3 = ffma2(a2[4 * j + 3], v2.y, s3);
            }
            float2 fs = upk2(add2(add2(s0, s1), add2(s2, s3)));
            float ex = fexp((fs.x + fs.y) * 0.015625f);
            Zacc += ex;
            u64t exd = pk2(ex, ex);
            const ulonglong2* Ep2 = (const ulonglong2*)&Es[q * 64];
#pragma unroll
            for (int j2 = 0; j2 < 16; j2++) {
                ulonglong2 ev = Ep2[j2];
                F2[2 * j2]     = ffma2(exd, ev.x, F2[2 * j2]);
                F2[2 * j2 + 1] = ffma2(exd, ev.y, F2[2 * j2 + 1]);
            }
        }
    }

    u64t* Fp = (u64t*)(F + (((long)(n * SEQ + r)) * SEQ + p) * 64);
#pragma unroll
    for (int j = 0; j < 32; j++) Fp[j] = F2[j];

    float zw = Zacc;
    for (int o = 16; o; o >>= 1) zw += __shfl_down_sync(~0u, zw, o);
    if ((p & 31) == 0) zred[p >> 5] = zw;
    __syncthreads();
    if (p == 0) {
        float zt = 0.f;
        for (int w = 0; w < 6; w++) zt += zred[w];
        Z[n * SEQ + r] = zt;
    }
}

extern "C" void kernel_launch(void* const* d_in, const int* in_sizes, int n_in,
                              void* d_out, int out_size) {
    const float* x       = (const float*)d_in[0];
    const float* ln_w    = (const float*)d_in[1];
    const float* ln_b    = (const float*)d_in[2];
    const float* W_abcde = (const float*)d_in[3];
    const float* b_abcde = (const float*)d_in[4];
    const float* W_K     = (const float*)d_in[5];
    const float* W_V     = (const float*)d_in[6];
    const float* W_out   = (const float*)d_in[7];
    const float* b_out   = (const float*)d_in[8];
    float* out = (float*)d_out;

    float *xn, *proj, *bsum, *wkr, *step1, *step2, *dT, *Epre, *F, *Z, *U, *zb;
    cudaGetSymbolAddress((void**)&xn, g_xn);
    cudaGetSymbolAddress((void**)&proj, g_proj);
    cudaGetSymbolAddress((void**)&bsum, g_bsum);
    cudaGetSymbolAddress((void**)&wkr, g_wkr);
    cudaGetSymbolAddress((void**)&step1, g_step1);
    cudaGetSymbolAddress((void**)&step2, g_step2);
    cudaGetSymbolAddress((void**)&dT, g_dT);
    cudaGetSymbolAddress((void**)&Epre, g_Epre);
    cudaGetSymbolAddress((void**)&F, g_F);
    cudaGetSymbolAddress((void**)&Z, g_Z);
    cudaGetSymbolAddress((void**)&U, g_U);
    cudaGetSymbolAddress((void**)&zb, g_zbuf);

    cudaFuncSetAttribute(attn_kernel, cudaFuncAttributeMaxDynamicSharedMemorySize, 98304);

    // 1
    ln_kernel<<<SEQ, 256>>>(x, ln_w, ln_b, xn);
    // 2: prefill proj with bias (atomic k-split GEMM adds on top)
    fillb_kernel<<<(SEQ * 2560 + 255) / 256, 256>>>(proj, b_abcde, SEQ * 2560, 2560);
    // 3
    reshape_wk<<<2048, 256>>>(W_K, wkr);
    // 4: proj (k-split 2, atomic)  <-- profiled slot
    gemm_kernel<<<dim3(40, 3, 2), 128>>>(xn, 512, 0, 0, W_abcde, 512, 1, 0, 0,
                                         proj, 2560, 0, 0, 0, 512, 1, 2, 1);
    // 5
    zero_kernel<<<(SEQ * 4096 + 255) / 256, 256>>>(step1, SEQ * 4096);
    // 6: step1 (k-split 2, atomic)
    gemm_kernel<<<dim3(64, 3, 2), 128>>>(proj + 1024, 2560, 0, 0, wkr, 512, 1, 0, 0,
                                         step1, 4096, 0, 0, 0, 512, 1, 2, 1);
    // 7
    bsum_kernel<<<48, 256>>>(proj, bsum);
    // 8
    dT_kernel<<<(NH * 64 * SEQ + 255) / 256, 256>>>(proj, dT);
    // 9
    epre_kernel<<<NH, 64>>>(proj, Epre);
    // 10: step2
    gemm_kernel<<<dim3(1, 3, 192), 128>>>(bsum, 64, 0, 0, step1, 64, 1, 4096, 0,
                                          step2, 64, 12288, 0, 0, 64, 192, 1, 0);
    // 11: attn
    attn_kernel<<<dim3(192, 8), 192, 98304>>>(proj, step2, Epre, F, Z);
    // 12: U
    gemm_kernel<<<dim3(1, 1, 1536), 128>>>(dT, 192, 0, 12288,
                                           F, 1, 64, 12288, 2359296,
                                           U, 64, 4096, 786432, 0, 192, 192, 1, 0);
    // 13-15: z
    zero_kernel<<<(SEQ * 512 + 255) / 256, 256>>>(zb, SEQ * 512);
    gemm_kernel<<<dim3(1, 3, 64), 128>>>(U, 4096, 786432, 0,
                                         W_V, 1, 64, 262144, 0,
                                         zb, 512, 64, 0, 0, 4096, 8, 8, 1);
    zscale_kernel<<<(SEQ * 512 + 255) / 256, 256>>>(zb, Z);
    // 16-17: out
    fillb_kernel<<<(SEQ * 512 + 255) / 256, 256>>>(out, b_out, SEQ * 512, 512);
    gemm_kernel<<<dim3(8, 3, 4), 128>>>(zb, 512, 0, 0, W_out, 512, 1, 0, 0,
                                        out, 512, 0, 0, 0, 512, 1, 4, 1);
}

// round 13
// speedup vs baseline: 1.2616x; 1.1774x over previous
#include <cuda_runtime.h>
#include <cuda_fp16.h>
#include <cstdint>

#define SEQ 192
#define NH 8

__device__ float g_xn[SEQ * 512];
__device__ float g_proj[SEQ * 2560];
__device__ float g_bsum[SEQ * 64];
__device__ float g_wkr[4096 * 512];
__device__ float g_step1[SEQ * 4096];
__device__ float g_step2[SEQ * SEQ * 64];
__device__ float g_U[NH * SEQ * 4096];
__device__ float g_zbuf[SEQ * 512];

typedef unsigned long long u64t;

__device__ __forceinline__ u64t pk2(float lo, float hi) {
    u64t d; asm("mov.b64 %0, {%1, %2};" : "=l"(d) : "f"(lo), "f"(hi)); return d;
}
__device__ __forceinline__ float2 upk2(u64t d) {
    float2 r; asm("mov.b64 {%0, %1}, %2;" : "=f"(r.x), "=f"(r.y) : "l"(d)); return r;
}
__device__ __forceinline__ u64t ffma2(u64t a, u64t b, u64t c) {
    u64t d; asm("fma.rn.f32x2 %0, %1, %2, %3;" : "=l"(d) : "l"(a), "l"(b), "l"(c)); return d;
}
__device__ __forceinline__ uint32_t pkh(float lo, float hi) {
    __half2 h = __floats2half2_rn(lo, hi);
    return *(uint32_t*)&h;
}

__device__ __forceinline__ float fexp(float x) {
    float t = fmaf(x, 1.4426950408889634f, 12582912.0f);
    float kf = t - 12582912.0f;
    int ki = (int)kf;
    float r = fmaf(kf, -0.69314718055994531f, x);
    float p = 1.38888889e-3f;
    p = fmaf(p, r, 8.33333333e-3f);
    p = fmaf(p, r, 4.16666667e-2f);
    p = fmaf(p, r, 1.66666667e-1f);
    p = fmaf(p, r, 0.5f);
    p = fmaf(p, r, 1.0f);
    p = fmaf(p, r, 1.0f);
    return p * __int_as_float((ki + 127) << 23);
}

__device__ __forceinline__ void mma_f16(float c[4], uint32_t a0, uint32_t a1,
                                        uint32_t a2, uint32_t a3,
                                        uint32_t b0, uint32_t b1) {
    asm volatile(
        "mma.sync.aligned.m16n8k16.row.col.f32.f16.f16.f32 "
        "{%0,%1,%2,%3}, {%4,%5,%6,%7}, {%8,%9}, {%0,%1,%2,%3};"
        : "+f"(c[0]), "+f"(c[1]), "+f"(c[2]), "+f"(c[3])
        : "r"(a0), "r"(a1), "r"(a2), "r"(a3), "r"(b0), "r"(b1));
}

// ---------------- LayerNorm ----------------
__global__ __launch_bounds__(256) void ln_kernel(const float* __restrict__ x,
                                                 const float* __restrict__ w,
                                                 const float* __restrict__ b,
                                                 float* __restrict__ xn) {
    __shared__ float rs[256], rq[256];
    int row = blockIdx.x, tid = threadIdx.x;
    float v0 = x[row * 512 + tid], v1 = x[row * 512 + 256 + tid];
    rs[tid] = v0 + v1;
    rq[tid] = v0 * v0 + v1 * v1;
    __syncthreads();
    for (int s = 128; s >= 32; s >>= 1) {
        if (tid < s) { rs[tid] += rs[tid + s]; rq[tid] += rq[tid + s]; }
        __syncthreads();
    }
    if (tid < 32) {
        float a = rs[tid], q = rq[tid];
        for (int o = 16; o; o >>= 1) {
            a += __shfl_down_sync(~0u, a, o);
            q += __shfl_down_sync(~0u, q, o);
        }
        if (!tid) { rs[0] = a; rq[0] = q; }
    }
    __syncthreads();
    float mu = rs[0] * (1.f / 512.f);
    float var = rq[0] * (1.f / 512.f) - mu * mu;
    float is = rsqrtf(var + 1e-5f);
    xn[row * 512 + tid]       = (v0 - mu) * is * w[tid]       + b[tid];
    xn[row * 512 + 256 + tid] = (v1 - mu) * is * w[256 + tid] + b[256 + tid];
}

// ---------------- 64x64 f32x2 GEMM (R4/R8 proven) ----------------
__global__ __launch_bounds__(128) void gemm_kernel(
    const float* __restrict__ A, int lda, long sA1, long sA2,
    const float* __restrict__ B, int ldbn, int ldbk, long sB1, long sB2,
    float* __restrict__ C, int ldc, long sC1, long sC2,
    const float* __restrict__ bias,
    int K, int nb1, int kSplits, int doAtomic)
{
    __shared__ float Ast[16][68];
    __shared__ float Bst[16][68];
    int z = blockIdx.z;
    int kz = z % kSplits;
    int t = z / kSplits;
    int b1 = t % nb1, b2 = t / nb1;
    A += b1 * sA1 + b2 * sA2;
    B += b1 * sB1 + b2 * sB2;
    C += b1 * sC1 + b2 * sC2;
    const int kPer = K / kSplits;
    const int k0 = kz * kPer, k1 = k0 + kPer;
    const int m0 = blockIdx.y * 64;
    const int n0 = blockIdx.x * 64;
    const int tid = threadIdx.x;
    const int tn0 = (tid & 15) * 4;
    const int tm0 = (tid >> 4) * 8;
    const int pbn = tid & 63;

    u64t acc[4][4];
#pragma unroll
    for (int i = 0; i < 4; i++)
#pragma unroll
        for (int j = 0; j < 4; j++) acc[i][j] = 0ULL;

    float4 pa[2], pb[2];
    float pbs[8];

#pragma unroll
    for (int j = 0; j < 2; j++) {
        int idx = tid + j * 128;
        pa[j] = *(const float4*)(A + (long)(m0 + (idx >> 2)) * lda + k0 + (idx & 3) * 4);
    }
    if (ldbk == 1) {
#pragma unroll
        for (int j = 0; j < 2; j++) {
            int idx = tid + j * 128;
            pb[j] = *(const float4*)(B + (long)(n0 + (idx >> 2)) * ldbn + k0 + (idx & 3) * 4);
        }
    } else {
#pragma unroll
        for (int j = 0; j < 8; j++) {
            int k = (tid + j * 128) >> 6;
            pbs[j] = B[(long)(k0 + k) * ldbk + (long)(n0 + pbn) * ldbn];
        }
    }

    for (int kk = k0; kk < k1; kk += 16) {
#pragma unroll
        for (int j = 0; j < 2; j++) {
            int idx = tid + j * 128;
            int m = idx >> 2, kq = (idx & 3) * 4;
            Ast[kq + 0][m] = pa[j].x; Ast[kq + 1][m] = pa[j].y;
            Ast[kq + 2][m] = pa[j].z; Ast[kq + 3][m] = pa[j].w;
        }
        if (ldbk == 1) {
#pragma unroll
            for (int j = 0; j < 2; j++) {
                int idx = tid + j * 128;
                int nn = idx >> 2, kq = (idx & 3) * 4;
                Bst[kq + 0][nn] = pb[j].x; Bst[kq + 1][nn] = pb[j].y;
                Bst[kq + 2][nn] = pb[j].z; Bst[kq + 3][nn] = pb[j].w;
            }
        } else {
#pragma unroll
            for (int j = 0; j < 8; j++) {
                int idx = tid + j * 128;
                Bst[idx >> 6][idx & 63] = pbs[j];
            }
        }
        __syncthreads();

        if (kk + 16 < k1) {
            int kn = kk + 16;
#pragma unroll
            for (int j = 0; j < 2; j++) {
                int idx = tid + j * 128;
                pa[j] = *(const float4*)(A + (long)(m0 + (idx >> 2)) * lda + kn + (idx & 3) * 4);
            }
            if (ldbk == 1) {
#pragma unroll
                for (int j = 0; j < 2; j++) {
                    int idx = tid + j * 128;
                    pb[j] = *(const float4*)(B + (long)(n0 + (idx >> 2)) * ldbn + kn + (idx & 3) * 4);
                }
            } else {
#pragma unroll
                for (int j = 0; j < 8; j++) {
                    int k = (tid + j * 128) >> 6;
                    pbs[j] = B[(long)(kn + k) * ldbk + (long)(n0 + pbn) * ldbn];
                }
            }
        }

#pragma unroll
        for (int k = 0; k < 16; k++) {
            ulonglong2 a01 = *(const ulonglong2*)&Ast[k][tm0];
            ulonglong2 a23 = *(const ulonglong2*)&Ast[k][tm0 + 4];
            float4 bv = *(const float4*)&Bst[k][tn0];
            u64t b0 = pk2(bv.x, bv.x), b1p = pk2(bv.y, bv.y);
            u64t b2p = pk2(bv.z, bv.z), b3p = pk2(bv.w, bv.w);
            acc[0][0] = ffma2(a01.x, b0, acc[0][0]);
            acc[0][1] = ffma2(a01.x, b1p, acc[0][1]);
            acc[0][2] = ffma2(a01.x, b2p, acc[0][2]);
            acc[0][3] = ffma2(a01.x, b3p, acc[0][3]);
            acc[1][0] = ffma2(a01.y, b0, acc[1][0]);
            acc[1][1] = ffma2(a01.y, b1p, acc[1][1]);
            acc[1][2] = ffma2(a01.y, b2p, acc[1][2]);
            acc[1][3] = ffma2(a01.y, b3p, acc[1][3]);
            acc[2][0] = ffma2(a23.x, b0, acc[2][0]);
            acc[2][1] = ffma2(a23.x, b1p, acc[2][1]);
            acc[2][2] = ffma2(a23.x, b2p, acc[2][2]);
            acc[2][3] = ffma2(a23.x, b3p, acc[2][3]);
            acc[3][0] = ffma2(a23.y, b0, acc[3][0]);
            acc[3][1] = ffma2(a23.y, b1p, acc[3][1]);
            acc[3][2] = ffma2(a23.y, b2p, acc[3][2]);
            acc[3][3] = ffma2(a23.y, b3p, acc[3][3]);
        }
        __syncthreads();
    }
#pragma unroll
    for (int mp = 0; mp < 4; mp++)
#pragma unroll
        for (int j = 0; j < 4; j++) {
            float2 v = upk2(acc[mp][j]);
            int m = m0 + tm0 + mp * 2;
            int nn = n0 + tn0 + j;
            if (doAtomic) {
                atomicAdd(&C[(long)m * ldc + nn], v.x);
                atomicAdd(&C[(long)(m + 1) * ldc + nn], v.y);
            } else {
                float bb = bias ? bias[nn] : 0.f;
                C[(long)m * ldc + nn] = v.x + bb;
                C[(long)(m + 1) * ldc + nn] = v.y + bb;
            }
        }
}

// ---------------- small helpers ----------------
__global__ void bsum_kernel(const float* __restrict__ proj, float* __restrict__ bs) {
    int idx = blockIdx.x * 256 + threadIdx.x;
    if (idx < SEQ * 64) {
        int q = idx >> 6, j = idx & 63;
        float s = 0.f;
#pragma unroll
        for (int nn = 0; nn < 8; nn++) s += proj[q * 2560 + 512 + nn * 64 + j];
        bs[idx] = s;
    }
}

__global__ void reshape_wk(const float* __restrict__ wk, float* __restrict__ out) {
    for (int o = blockIdx.x * blockDim.x + threadIdx.x; o < 4096 * 512;
         o += gridDim.x * blockDim.x) {
        int ij = o >> 9, nk = o & 511;
        int n = nk >> 6, k = nk & 63;
        int i = ij >> 6, j = ij & 63;
        out[o] = wk[n * 262144 + i * 4096 + j * 64 + k];
    }
}

__global__ void zero_kernel(float* p, int n) {
    int i = blockIdx.x * 256 + threadIdx.x;
    if (i < n) p[i] = 0.f;
}

__global__ void fillb_kernel(float* __restrict__ C, const float* __restrict__ bias,
                             int n, int ldm) {
    int i = blockIdx.x * 256 + threadIdx.x;
    if (i < n) C[i] = bias[i % ldm];
}

// ---------------- fused attention via mma.sync fp16 + deviation decomposition --
// E = 1 + D (masked D = 0); F = Etot[g] + D@e; U = dsum[h]*Etot[g] + dT@(D@e).
// One CTA per (r, n), 6 warps. smem:
//   Aa  [192][72]  half  @0        A_n (p x i)
//   S2P [32][200]  u32   @27648    step2 k-pairs x q
//   eP  [96][72]   u32   @53248    e k-pairs x g
//   dTs [64][200]  half  @80896    dT (h x p)
//   Es  [192][200] half  @106496   D (p x q)
//   Fs  [192][72]  half  @183296   DF (p x g)
__global__ __launch_bounds__(192, 1) void attn_mma_kernel(
    const float* __restrict__ proj, const float* __restrict__ step2,
    float* __restrict__ Uout)
{
    extern __shared__ char smem[];
    __half* Aa = (__half*)smem;
    uint32_t* S2P = (uint32_t*)(smem + 27648);
    uint32_t* eP  = (uint32_t*)(smem + 53248);
    __half* dTs = (__half*)(smem + 80896);
    __half* Es  = (__half*)(smem + 106496);
    __half* Fs  = (__half*)(smem + 183296);
    __shared__ float zred[6];
    __shared__ float s_invZ;
    __shared__ float sEtot[64];
    __shared__ float sdsum[64];

    int r = blockIdx.x, n = blockIdx.y, tid = threadIdx.x;
    int wid = tid >> 5, lane = tid & 31;
    int g = lane >> 2, tig = lane & 3;

    // -- exact fp32 uniform-part reductions (r-independent) --
    if (tid < 64) {
        float s = 0.f;
#pragma unroll 4
        for (int q = 0; q < SEQ; q++) s += proj[q * 2560 + 2048 + n * 64 + tid];
        sEtot[tid] = s;
    } else if (tid < 128) {
        int h = tid - 64;
        float s = 0.f;
#pragma unroll 4
        for (int p = 0; p < SEQ; p++) s += proj[p * 2560 + 1536 + n * 64 + h];
        sdsum[h] = s;
    }

    // -- stage inputs --
    for (int idx = tid; idx < 3072; idx += 192) {           // Aa
        int p = idx >> 4, i4 = (idx & 15) * 4;
        float4 v = *(const float4*)(proj + p * 2560 + n * 64 + i4);
        uint32_t* d = (uint32_t*)&Aa[p * 72 + i4];
        d[0] = pkh(v.x, v.y); d[1] = pkh(v.z, v.w);
    }
    for (int idx = tid; idx < 6144; idx += 192) {           // S2P[ik][q]
        int ik = idx / 192, q = idx - ik * 192;
        float2 v = *(const float2*)(step2 + (long)r * 12288 + q * 64 + 2 * ik);
        S2P[ik * 200 + q] = pkh(v.x, v.y);
    }
    for (int idx = tid; idx < 6144; idx += 192) {           // eP[jk][g]
        int jk = idx >> 6, gg = idx & 63;
        float lo = proj[(2 * jk) * 2560 + 2048 + n * 64 + gg];
        float hi = proj[(2 * jk + 1) * 2560 + 2048 + n * 64 + gg];
        eP[jk * 72 + gg] = pkh(lo, hi);
    }
    for (int idx = tid; idx < 12288; idx += 192) {          // dTs[h][p]
        int p = idx >> 6, h = idx & 63;
        dTs[h * 200 + p] = __float2half_rn(proj[p * 2560 + 1536 + n * 64 + h]);
    }
    __syncthreads();

    // -- GEMM1: S = Aa @ S2^T; epilogue D = masked(exp(S/64)-1) -> Es, Z --
    float zpart = 0.f;
#pragma unroll
    for (int mt = 0; mt < 2; mt++) {
        int m0 = wid * 32 + mt * 16;
        uint32_t af[4][4];
#pragma unroll
        for (int kk = 0; kk < 4; kk++) {
            af[kk][0] = *(uint32_t*)&Aa[(m0 + g) * 72 + kk * 16 + 2 * tig];
            af[kk][1] = *(uint32_t*)&Aa[(m0 + g + 8) * 72 + kk * 16 + 2 * tig];
            af[kk][2] = *(uint32_t*)&Aa[(m0 + g) * 72 + kk * 16 + 2 * tig + 8];
            af[kk][3] = *(uint32_t*)&Aa[(m0 + g + 8) * 72 + kk * 16 + 2 * tig + 8];
        }
        for (int nb = 0; nb < 24; nb++) {
            float c[4] = {0.f, 0.f, 0.f, 0.f};
#pragma unroll
            for (int kk = 0; kk < 4; kk++) {
                uint32_t b0 = S2P[(kk * 8 + tig) * 200 + nb * 8 + g];
                uint32_t b1 = S2P[(kk * 8 + tig + 4) * 200 + nb * 8 + g];
                mma_f16(c, af[kk][0], af[kk][1], af[kk][2], af[kk][3], b0, b1);
            }
            int p0 = m0 + g, p1 = p0 + 8, q0 = nb * 8 + 2 * tig;
            float d00 = (q0     <= p0) ? 0.0f : fexp(c[0] * 0.015625f) - 1.0f;
            float d01 = (q0 + 1 <= p0) ? 0.0f : fexp(c[1] * 0.015625f) - 1.0f;
            float d10 = (q0     <= p1) ? 0.0f : fexp(c[2] * 0.015625f) - 1.0f;
            float d11 = (q0 + 1 <= p1) ? 0.0f : fexp(c[3] * 0.015625f) - 1.0f;
            zpart += (d00 + d01) + (d10 + d11);
            *(uint32_t*)&Es[p0 * 200 + q0] = pkh(d00, d01);
            *(uint32_t*)&Es[p1 * 200 + q0] = pkh(d10, d11);
        }
    }
    for (int o = 16; o; o >>= 1) zpart += __shfl_down_sync(~0u, zpart, o);
    if (lane == 0) zred[wid] = zpart;
    __syncthreads();
    if (tid == 0) {
        float zt = 36864.0f;   // 192*192 ones + sum of deviations
        for (int w = 0; w < 6; w++) zt += zred[w];
        s_invZ = 1.0f / zt;
    }

    // -- GEMM2: DF = D @ e -> Fs --
#pragma unroll
    for (int mt = 0; mt < 2; mt++) {
        int m0 = wid * 32 + mt * 16;
        for (int nb = 0; nb < 8; nb++) {
            float c[4] = {0.f, 0.f, 0.f, 0.f};
#pragma unroll
            for (int kk = 0; kk < 12; kk++) {
                uint32_t a0 = *(uint32_t*)&Es[(m0 + g) * 200 + kk * 16 + 2 * tig];
                uint32_t a1 = *(uint32_t*)&Es[(m0 + g + 8) * 200 + kk * 16 + 2 * tig];
                uint32_t a2 = *(uint32_t*)&Es[(m0 + g) * 200 + kk * 16 + 2 * tig + 8];
                uint32_t a3 = *(uint32_t*)&Es[(m0 + g + 8) * 200 + kk * 16 + 2 * tig + 8];
                uint32_t b0 = eP[(kk * 8 + tig) * 72 + nb * 8 + g];
                uint32_t b1 = eP[(kk * 8 + tig + 4) * 72 + nb * 8 + g];
                mma_f16(c, a0, a1, a2, a3, b0, b1);
            }
            int p0 = m0 + g, p1 = p0 + 8, g0 = nb * 8 + 2 * tig;
            *(uint32_t*)&Fs[p0 * 72 + g0] = pkh(c[0], c[1]);
            *(uint32_t*)&Fs[p1 * 72 + g0] = pkh(c[2], c[3]);
        }
    }
    __syncthreads();

    // -- GEMM3: U = dsum*Etot + dTs @ Fs (warps 0-3), scaled by invZ --
    if (wid < 4) {
        int m0 = wid * 16;
        float invZ = s_invZ;
        for (int nb = 0; nb < 8; nb++) {
            float c[4] = {0.f, 0.f, 0.f, 0.f};
#pragma unroll
            for (int kk = 0; kk < 12; kk++) {
                uint32_t a0 = *(uint32_t*)&dTs[(m0 + g) * 200 + kk * 16 + 2 * tig];
                uint32_t a1 = *(uint32_t*)&dTs[(m0 + g + 8) * 200 + kk * 16 + 2 * tig];
                uint32_t a2 = *(uint32_t*)&dTs[(m0 + g) * 200 + kk * 16 + 2 * tig + 8];
                uint32_t a3 = *(uint32_t*)&dTs[(m0 + g + 8) * 200 + kk * 16 + 2 * tig + 8];
                int k0 = kk * 16 + 2 * tig;
                uint32_t b0 = (uint32_t)*(unsigned short*)&Fs[k0 * 72 + nb * 8 + g]
                            | ((uint32_t)*(unsigned short*)&Fs[(k0 + 1) * 72 + nb * 8 + g] << 16);
                uint32_t b1 = (uint32_t)*(unsigned short*)&Fs[(k0 + 8) * 72 + nb * 8 + g]
                            | ((uint32_t)*(unsigned short*)&Fs[(k0 + 9) * 72 + nb * 8 + g] << 16);
                mma_f16(c, a0, a1, a2, a3, b0, b1);
            }
            int h0 = m0 + g, h1 = h0 + 8, g0 = nb * 8 + 2 * tig;
            float* up = Uout + ((long)n * SEQ + r) * 4096;
            float e0 = sEtot[g0], e1 = sEtot[g0 + 1];
            float ds0 = sdsum[h0], ds1 = sdsum[h1];
            *(float2*)(up + h0 * 64 + g0) =
                make_float2((ds0 * e0 + c[0]) * invZ, (ds0 * e1 + c[1]) * invZ);
            *(float2*)(up + h1 * 64 + g0) =
                make_float2((ds1 * e0 + c[2]) * invZ, (ds1 * e1 + c[3]) * invZ);
        }
    }
}

extern "C" void kernel_launch(void* const* d_in, const int* in_sizes, int n_in,
                              void* d_out, int out_size) {
    const float* x       = (const float*)d_in[0];
    const float* ln_w    = (const float*)d_in[1];
    const float* ln_b    = (const float*)d_in[2];
    const float* W_abcde = (const float*)d_in[3];
    const float* b_abcde = (const float*)d_in[4];
    const float* W_K     = (const float*)d_in[5];
    const float* W_V     = (const float*)d_in[6];
    const float* W_out   = (const float*)d_in[7];
    const float* b_out   = (const float*)d_in[8];
    float* out = (float*)d_out;

    float *xn, *proj, *bsum, *wkr, *step1, *step2, *U, *zb;
    cudaGetSymbolAddress((void**)&xn, g_xn);
    cudaGetSymbolAddress((void**)&proj, g_proj);
    cudaGetSymbolAddress((void**)&bsum, g_bsum);
    cudaGetSymbolAddress((void**)&wkr, g_wkr);
    cudaGetSymbolAddress((void**)&step1, g_step1);
    cudaGetSymbolAddress((void**)&step2, g_step2);
    cudaGetSymbolAddress((void**)&U, g_U);
    cudaGetSymbolAddress((void**)&zb, g_zbuf);

    cudaFuncSetAttribute(attn_mma_kernel, cudaFuncAttributeMaxDynamicSharedMemorySize, 210944);

    ln_kernel<<<SEQ, 256>>>(x, ln_w, ln_b, xn);
    fillb_kernel<<<(SEQ * 2560 + 255) / 256, 256>>>(proj, b_abcde, SEQ * 2560, 2560);
    reshape_wk<<<2048, 256>>>(W_K, wkr);
    gemm_kernel<<<dim3(40, 3, 2), 128>>>(xn, 512, 0, 0, W_abcde, 512, 1, 0, 0,
                                         proj, 2560, 0, 0, 0, 512, 1, 2, 1);
    zero_kernel<<<(SEQ * 4096 + 255) / 256, 256>>>(step1, SEQ * 4096);
    gemm_kernel<<<dim3(64, 3, 2), 128>>>(proj + 1024, 2560, 0, 0, wkr, 512, 1, 0, 0,
                                         step1, 4096, 0, 0, 0, 512, 1, 2, 1);
    bsum_kernel<<<48, 256>>>(proj, bsum);
    gemm_kernel<<<dim3(1, 3, 192), 128>>>(bsum, 64, 0, 0, step1, 64, 1, 4096, 0,
                                          step2, 64, 12288, 0, 0, 64, 192, 1, 0);
    // fused tensor-core attention -> U (1/Z folded in)
    attn_mma_kernel<<<dim3(SEQ, NH), 192, 210944>>>(proj, step2, U);
    // z = U @ W_V
    zero_kernel<<<(SEQ * 512 + 255) / 256, 256>>>(zb, SEQ * 512);
    gemm_kernel<<<dim3(1, 3, 64), 128>>>(U, 4096, 786432, 0,
                                         W_V, 1, 64, 262144, 0,
                                         zb, 512, 64, 0, 0, 4096, 8, 8, 1);
    // out = z @ W_out^T + b_out
    fillb_kernel<<<(SEQ * 512 + 255) / 256, 256>>>(out, b_out, SEQ * 512, 512);
    gemm_kernel<<<dim3(8, 3, 4), 128>>>(zb, 512, 0, 0, W_out, 512, 1, 0, 0,
                                        out, 512, 0, 0, 0, 512, 1, 4, 1);
}

// round 16
// speedup vs baseline: 1.7452x; 1.3834x over previous
#include <cuda_runtime.h>
#include <cuda_fp16.h>
#include <cstdint>

#define SEQ 192
#define NH 8

__device__ float g_xn[SEQ * 512];
__device__ float g_proj[SEQ * 2560];
__device__ float g_bsum[SEQ * 64];
__device__ float g_wkr[4096 * 512];
__device__ float g_step1[SEQ * 4096];
__device__ float g_step2[SEQ * SEQ * 64];
__device__ float g_U[NH * SEQ * 4096];
__device__ float g_zbuf[SEQ * 512];
__device__ uint32_t g_pA[NH * 6144];
__device__ uint32_t g_pE[NH * 6144];
__device__ uint32_t g_pdT[NH * 6144];
__device__ uint32_t g_pS2[(long)SEQ * 6144];
__device__ float g_Etot[NH * 64];
__device__ float g_dsum[NH * 64];

typedef unsigned long long u64t;

__device__ __forceinline__ u64t pk2(float lo, float hi) {
    u64t d; asm("mov.b64 %0, {%1, %2};" : "=l"(d) : "f"(lo), "f"(hi)); return d;
}
__device__ __forceinline__ float2 upk2(u64t d) {
    float2 r; asm("mov.b64 {%0, %1}, %2;" : "=f"(r.x), "=f"(r.y) : "l"(d)); return r;
}
__device__ __forceinline__ u64t ffma2(u64t a, u64t b, u64t c) {
    u64t d; asm("fma.rn.f32x2 %0, %1, %2, %3;" : "=l"(d) : "l"(a), "l"(b), "l"(c)); return d;
}
__device__ __forceinline__ uint32_t pkh(float lo, float hi) {
    __half2 h = __floats2half2_rn(lo, hi);
    return *(uint32_t*)&h;
}

__device__ __forceinline__ float fexp(float x) {
    float t = fmaf(x, 1.4426950408889634f, 12582912.0f);
    float kf = t - 12582912.0f;
    int ki = (int)kf;
    float r = fmaf(kf, -0.69314718055994531f, x);
    float p = 1.38888889e-3f;
    p = fmaf(p, r, 8.33333333e-3f);
    p = fmaf(p, r, 4.16666667e-2f);
    p = fmaf(p, r, 1.66666667e-1f);
    p = fmaf(p, r, 0.5f);
    p = fmaf(p, r, 1.0f);
    p = fmaf(p, r, 1.0f);
    return p * __int_as_float((ki + 127) << 23);
}

__device__ __forceinline__ void mma_f16(float c[4], uint32_t a0, uint32_t a1,
                                        uint32_t a2, uint32_t a3,
                                        uint32_t b0, uint32_t b1) {
    asm volatile(
        "mma.sync.aligned.m16n8k16.row.col.f32.f16.f16.f32 "
        "{%0,%1,%2,%3}, {%4,%5,%6,%7}, {%8,%9}, {%0,%1,%2,%3};"
        : "+f"(c[0]), "+f"(c[1]), "+f"(c[2]), "+f"(c[3])
        : "r"(a0), "r"(a1), "r"(a2), "r"(a3), "r"(b0), "r"(b1));
}

// ---------------- LayerNorm ----------------
__global__ __launch_bounds__(256) void ln_kernel(const float* __restrict__ x,
                                                 const float* __restrict__ w,
                                                 const float* __restrict__ b,
                                                 float* __restrict__ xn) {
    __shared__ float rs[256], rq[256];
    int row = blockIdx.x, tid = threadIdx.x;
    float v0 = x[row * 512 + tid], v1 = x[row * 512 + 256 + tid];
    rs[tid] = v0 + v1;
    rq[tid] = v0 * v0 + v1 * v1;
    __syncthreads();
    for (int s = 128; s >= 32; s >>= 1) {
        if (tid < s) { rs[tid] += rs[tid + s]; rq[tid] += rq[tid + s]; }
        __syncthreads();
    }
    if (tid < 32) {
        float a = rs[tid], q = rq[tid];
        for (int o = 16; o; o >>= 1) {
            a += __shfl_down_sync(~0u, a, o);
            q += __shfl_down_sync(~0u, q, o);
        }
        if (!tid) { rs[0] = a; rq[0] = q; }
    }
    __syncthreads();
    float mu = rs[0] * (1.f / 512.f);
    float var = rq[0] * (1.f / 512.f) - mu * mu;
    float is = rsqrtf(var + 1e-5f);
    xn[row * 512 + tid]       = (v0 - mu) * is * w[tid]       + b[tid];
    xn[row * 512 + 256 + tid] = (v1 - mu) * is * w[256 + tid] + b[256 + tid];
}

// ---------------- 64x64 f32x2 GEMM (proven) ----------------
__global__ __launch_bounds__(128) void gemm_kernel(
    const float* __restrict__ A, int lda, long sA1, long sA2,
    const float* __restrict__ B, int ldbn, int ldbk, long sB1, long sB2,
    float* __restrict__ C, int ldc, long sC1, long sC2,
    const float* __restrict__ bias,
    int K, int nb1, int kSplits, int doAtomic)
{
    __shared__ float Ast[16][68];
    __shared__ float Bst[16][68];
    int z = blockIdx.z;
    int kz = z % kSplits;
    int t = z / kSplits;
    int b1 = t % nb1, b2 = t / nb1;
    A += b1 * sA1 + b2 * sA2;
    B += b1 * sB1 + b2 * sB2;
    C += b1 * sC1 + b2 * sC2;
    const int kPer = K / kSplits;
    const int k0 = kz * kPer, k1 = k0 + kPer;
    const int m0 = blockIdx.y * 64;
    const int n0 = blockIdx.x * 64;
    const int tid = threadIdx.x;
    const int tn0 = (tid & 15) * 4;
    const int tm0 = (tid >> 4) * 8;
    const int pbn = tid & 63;

    u64t acc[4][4];
#pragma unroll
    for (int i = 0; i < 4; i++)
#pragma unroll
        for (int j = 0; j < 4; j++) acc[i][j] = 0ULL;

    float4 pa[2], pb[2];
    float pbs[8];

#pragma unroll
    for (int j = 0; j < 2; j++) {
        int idx = tid + j * 128;
        pa[j] = *(const float4*)(A + (long)(m0 + (idx >> 2)) * lda + k0 + (idx & 3) * 4);
    }
    if (ldbk == 1) {
#pragma unroll
        for (int j = 0; j < 2; j++) {
            int idx = tid + j * 128;
            pb[j] = *(const float4*)(B + (long)(n0 + (idx >> 2)) * ldbn + k0 + (idx & 3) * 4);
        }
    } else {
#pragma unroll
        for (int j = 0; j < 8; j++) {
            int k = (tid + j * 128) >> 6;
            pbs[j] = B[(long)(k0 + k) * ldbk + (long)(n0 + pbn) * ldbn];
        }
    }

    for (int kk = k0; kk < k1; kk += 16) {
#pragma unroll
        for (int j = 0; j < 2; j++) {
            int idx = tid + j * 128;
            int m = idx >> 2, kq = (idx & 3) * 4;
            Ast[kq + 0][m] = pa[j].x; Ast[kq + 1][m] = pa[j].y;
            Ast[kq + 2][m] = pa[j].z; Ast[kq + 3][m] = pa[j].w;
        }
        if (ldbk == 1) {
#pragma unroll
            for (int j = 0; j < 2; j++) {
                int idx = tid + j * 128;
                int nn = idx >> 2, kq = (idx & 3) * 4;
                Bst[kq + 0][nn] = pb[j].x; Bst[kq + 1][nn] = pb[j].y;
                Bst[kq + 2][nn] = pb[j].z; Bst[kq + 3][nn] = pb[j].w;
            }
        } else {
#pragma unroll
            for (int j = 0; j < 8; j++) {
                int idx = tid + j * 128;
                Bst[idx >> 6][idx & 63] = pbs[j];
            }
        }
        __syncthreads();

        if (kk + 16 < k1) {
            int kn = kk + 16;
#pragma unroll
            for (int j = 0; j < 2; j++) {
                int idx = tid + j * 128;
                pa[j] = *(const float4*)(A + (long)(m0 + (idx >> 2)) * lda + kn + (idx & 3) * 4);
            }
            if (ldbk == 1) {
#pragma unroll
                for (int j = 0; j < 2; j++) {
                    int idx = tid + j * 128;
                    pb[j] = *(const float4*)(B + (long)(n0 + (idx >> 2)) * ldbn + kn + (idx & 3) * 4);
                }
            } else {
#pragma unroll
                for (int j = 0; j < 8; j++) {
                    int k = (tid + j * 128) >> 6;
                    pbs[j] = B[(long)(kn + k) * ldbk + (long)(n0 + pbn) * ldbn];
                }
            }
        }

#pragma unroll
        for (int k = 0; k < 16; k++) {
            ulonglong2 a01 = *(const ulonglong2*)&Ast[k][tm0];
            ulonglong2 a23 = *(const ulonglong2*)&Ast[k][tm0 + 4];
            float4 bv = *(const float4*)&Bst[k][tn0];
            u64t b0 = pk2(bv.x, bv.x), b1p = pk2(bv.y, bv.y);
            u64t b2p = pk2(bv.z, bv.z), b3p = pk2(bv.w, bv.w);
            acc[0][0] = ffma2(a01.x, b0, acc[0][0]);
            acc[0][1] = ffma2(a01.x, b1p, acc[0][1]);
            acc[0][2] = ffma2(a01.x, b2p, acc[0][2]);
            acc[0][3] = ffma2(a01.x, b3p, acc[0][3]);
            acc[1][0] = ffma2(a01.y, b0, acc[1][0]);
            acc[1][1] = ffma2(a01.y, b1p, acc[1][1]);
            acc[1][2] = ffma2(a01.y, b2p, acc[1][2]);
            acc[1][3] = ffma2(a01.y, b3p, acc[1][3]);
            acc[2][0] = ffma2(a23.x, b0, acc[2][0]);
            acc[2][1] = ffma2(a23.x, b1p, acc[2][1]);
            acc[2][2] = ffma2(a23.x, b2p, acc[2][2]);
            acc[2][3] = ffma2(a23.x, b3p, acc[2][3]);
            acc[3][0] = ffma2(a23.y, b0, acc[3][0]);
            acc[3][1] = ffma2(a23.y, b1p, acc[3][1]);
            acc[3][2] = ffma2(a23.y, b2p, acc[3][2]);
            acc[3][3] = ffma2(a23.y, b3p, acc[3][3]);
        }
        __syncthreads();
    }
#pragma unroll
    for (int mp = 0; mp < 4; mp++)
#pragma unroll
        for (int j = 0; j < 4; j++) {
            float2 v = upk2(acc[mp][j]);
            int m = m0 + tm0 + mp * 2;
            int nn = n0 + tn0 + j;
            if (doAtomic) {
                atomicAdd(&C[(long)m * ldc + nn], v.x);
                atomicAdd(&C[(long)(m + 1) * ldc + nn], v.y);
            } else {
                float bb = bias ? bias[nn] : 0.f;
                C[(long)m * ldc + nn] = v.x + bb;
                C[(long)(m + 1) * ldc + nn] = v.y + bb;
            }
        }
}

// ---------------- small helpers ----------------
__global__ void bsum_kernel(const float* __restrict__ proj, float* __restrict__ bs) {
    int idx = blockIdx.x * 256 + threadIdx.x;
    if (idx < SEQ * 64) {
        int q = idx >> 6, j = idx & 63;
        float s = 0.f;
#pragma unroll
        for (int nn = 0; nn < 8; nn++) s += proj[q * 2560 + 512 + nn * 64 + j];
        bs[idx] = s;
    }
}

__global__ void reshape_wk(const float* __restrict__ wk, float* __restrict__ out) {
    for (int o = blockIdx.x * blockDim.x + threadIdx.x; o < 4096 * 512;
         o += gridDim.x * blockDim.x) {
        int ij = o >> 9, nk = o & 511;
        int n = nk >> 6, k = nk & 63;
        int i = ij >> 6, j = ij & 63;
        out[o] = wk[n * 262144 + i * 4096 + j * 64 + k];
    }
}

__global__ void zero_kernel(float* p, int n) {
    int i = blockIdx.x * 256 + threadIdx.x;
    if (i < n) p[i] = 0.f;
}

__global__ void fillb_kernel(float* __restrict__ C, const float* __restrict__ bias,
                             int n, int ldm) {
    int i = blockIdx.x * 256 + threadIdx.x;
    if (i < n) C[i] = bias[i % ldm];
}

// pack per-head tensors: A pairs, e pairs, dT pairs, Etot, dsum
__global__ __launch_bounds__(256) void packn_kernel(
    const float* __restrict__ proj, uint32_t* __restrict__ gA,
    uint32_t* __restrict__ geP, uint32_t* __restrict__ gdT,
    float* __restrict__ gEt, float* __restrict__ gds)
{
    int n = blockIdx.x, tid = threadIdx.x;
    for (int idx = tid; idx < 6144; idx += 256) {
        int p = idx >> 5, i2 = idx & 31;
        float2 v = *(const float2*)(proj + p * 2560 + n * 64 + 2 * i2);
        gA[n * 6144 + idx] = pkh(v.x, v.y);
    }
    for (int idx = tid; idx < 6144; idx += 256) {
        int jk = idx >> 6, gg = idx & 63;
        float lo = proj[(2 * jk) * 2560 + 2048 + n * 64 + gg];
        float hi = proj[(2 * jk + 1) * 2560 + 2048 + n * 64 + gg];
        geP[n * 6144 + idx] = pkh(lo, hi);
    }
    for (int idx = tid; idx < 6144; idx += 256) {
        int h = idx / 96, pw = idx - h * 96;
        float lo = proj[(2 * pw) * 2560 + 1536 + n * 64 + h];
        float hi = proj[(2 * pw + 1) * 2560 + 1536 + n * 64 + h];
        gdT[n * 6144 + idx] = pkh(lo, hi);
    }
    if (tid < 64) {
        float s = 0.f, s2 = 0.f;
        for (int q = 0; q < SEQ; q++) {
            s  += proj[q * 2560 + 2048 + n * 64 + tid];
            s2 += proj[q * 2560 + 1536 + n * 64 + tid];
        }
        gEt[n * 64 + tid] = s;
        gds[n * 64 + tid] = s2;
    }
}

// pack step2 -> half pairs, transposed [r][ik][q] via smem (pad 65 -> conflict-free)
__global__ __launch_bounds__(256) void packs2_kernel(
    const float* __restrict__ step2, uint32_t* __restrict__ gS2)
{
    __shared__ float s[SEQ * 65];
    int r = blockIdx.x, tid = threadIdx.x;
    for (int idx = tid; idx < 12288; idx += 256) {
        int q = idx >> 6, i = idx & 63;
        s[q * 65 + i] = step2[(long)r * 12288 + idx];
    }
    __syncthreads();
    for (int idx = tid; idx < 6144; idx += 256) {
        int ik = idx / 192, q = idx - ik * 192;
        gS2[(long)r * 6144 + idx] = pkh(s[q * 65 + 2 * ik], s[q * 65 + 2 * ik + 1]);
    }
}

// ---------------- fused attention, 12 warps, packed inputs ----------------
__global__ __launch_bounds__(384, 1) void attn_mma_kernel(
    const uint32_t* __restrict__ gA, const uint32_t* __restrict__ geP,
    const uint32_t* __restrict__ gdT, const uint32_t* __restrict__ gS2,
    const float* __restrict__ gEt, const float* __restrict__ gds,
    float* __restrict__ Uout)
{
    extern __shared__ char smem[];
    __half* Aa = (__half*)smem;               // 192 x 72 half
    uint32_t* S2P = (uint32_t*)(smem + 27648);// 32 x 200 u32
    uint32_t* eP  = (uint32_t*)(smem + 53248);// 96 x 72 u32
    __half* dTs = (__half*)(smem + 80896);    // 64 x 200 half
    __half* Es  = (__half*)(smem + 106496);   // 192 x 200 half
    __half* Fs  = (__half*)(smem + 183296);   // 192 x 72 half
    __shared__ float zred[12];
    __shared__ float s_invZ;
    __shared__ float sEtot[64];
    __shared__ float sdsum[64];

    int r = blockIdx.x, n = blockIdx.y, tid = threadIdx.x;
    int wid = tid >> 5, lane = tid & 31;
    int g = lane >> 2, tig = lane & 3;

    if (tid < 64) sEtot[tid] = gEt[n * 64 + tid];
    else if (tid < 128) sdsum[tid - 64] = gds[n * 64 + tid - 64];

    uint32_t* Aa32 = (uint32_t*)Aa;
    uint32_t* dTs32 = (uint32_t*)dTs;
    for (int idx = tid; idx < 6144; idx += 384) {
        int p = idx >> 5, i2 = idx & 31;
        Aa32[p * 36 + i2] = gA[n * 6144 + idx];
    }
    for (int idx = tid; idx < 6144; idx += 384) {
        int jk = idx >> 6, gg = idx & 63;
        eP[jk * 72 + gg] = geP[n * 6144 + idx];
    }
    for (int idx = tid; idx < 6144; idx += 384) {
        int h = idx / 96, pw = idx - h * 96;
        dTs32[h * 100 + pw] = gdT[n * 6144 + idx];
    }
    for (int idx = tid; idx < 6144; idx += 384) {
        int ik = idx / 192, q = idx - ik * 192;
        S2P[ik * 200 + q] = gS2[(long)r * 6144 + idx];
    }
    __syncthreads();

    // -- GEMM1: warp-private 16-row m-tile; D = masked(exp(S/64)-1) -> Es --
    int m0 = wid * 16;
    uint32_t af[4][4];
#pragma unroll
    for (int kk = 0; kk < 4; kk++) {
        af[kk][0] = *(uint32_t*)&Aa[(m0 + g) * 72 + kk * 16 + 2 * tig];
        af[kk][1] = *(uint32_t*)&Aa[(m0 + g + 8) * 72 + kk * 16 + 2 * tig];
        af[kk][2] = *(uint32_t*)&Aa[(m0 + g) * 72 + kk * 16 + 2 * tig + 8];
        af[kk][3] = *(uint32_t*)&Aa[(m0 + g + 8) * 72 + kk * 16 + 2 * tig + 8];
    }
    float zpart = 0.f;
    for (int nb = 0; nb < 24; nb++) {
        float c[4] = {0.f, 0.f, 0.f, 0.f};
#pragma unroll
        for (int kk = 0; kk < 4; kk++) {
            uint32_t b0 = S2P[(kk * 8 + tig) * 200 + nb * 8 + g];
            uint32_t b1 = S2P[(kk * 8 + tig + 4) * 200 + nb * 8 + g];
            mma_f16(c, af[kk][0], af[kk][1], af[kk][2], af[kk][3], b0, b1);
        }
        int p0 = m0 + g, p1 = p0 + 8, q0 = nb * 8 + 2 * tig;
        float d00 = (q0     <= p0) ? 0.0f : fexp(c[0] * 0.015625f) - 1.0f;
        float d01 = (q0 + 1 <= p0) ? 0.0f : fexp(c[1] * 0.015625f) - 1.0f;
        float d10 = (q0     <= p1) ? 0.0f : fexp(c[2] * 0.015625f) - 1.0f;
        float d11 = (q0 + 1 <= p1) ? 0.0f : fexp(c[3] * 0.015625f) - 1.0f;
        zpart += (d00 + d01) + (d10 + d11);
        *(uint32_t*)&Es[p0 * 200 + q0] = pkh(d00, d01);
        *(uint32_t*)&Es[p1 * 200 + q0] = pkh(d10, d11);
    }
    for (int o = 16; o; o >>= 1) zpart += __shfl_down_sync(~0u, zpart, o);
    if (lane == 0) zred[wid] = zpart;

    // -- GEMM2 (warp-private rows): DF = D @ e -> Fs --
    for (int nb = 0; nb < 8; nb++) {
        float c[4] = {0.f, 0.f, 0.f, 0.f};
#pragma unroll
        for (int kk = 0; kk < 12; kk++) {
            uint32_t a0 = *(uint32_t*)&Es[(m0 + g) * 200 + kk * 16 + 2 * tig];
            uint32_t a1 = *(uint32_t*)&Es[(m0 + g + 8) * 200 + kk * 16 + 2 * tig];
            uint32_t a2 = *(uint32_t*)&Es[(m0 + g) * 200 + kk * 16 + 2 * tig + 8];
            uint32_t a3 = *(uint32_t*)&Es[(m0 + g + 8) * 200 + kk * 16 + 2 * tig + 8];
            uint32_t b0 = eP[(kk * 8 + tig) * 72 + nb * 8 + g];
            uint32_t b1 = eP[(kk * 8 + tig + 4) * 72 + nb * 8 + g];
            mma_f16(c, a0, a1, a2, a3, b0, b1);
        }
        int p0 = m0 + g, p1 = p0 + 8, g0 = nb * 8 + 2 * tig;
        *(uint32_t*)&Fs[p0 * 72 + g0] = pkh(c[0], c[1]);
        *(uint32_t*)&Fs[p1 * 72 + g0] = pkh(c[2], c[3]);
    }
    __syncthreads();
    if (tid == 0) {
        float zt = 36864.0f;
        for (int w = 0; w < 12; w++) zt += zred[w];
        s_invZ = 1.0f / zt;
    }
    __syncthreads();

    // -- GEMM3: U = dsum*Etot + dTs @ Fs; 32 tiles over 12 warps --
    float invZ = s_invZ;
    for (int t = wid; t < 32; t += 12) {
        int m3 = (t >> 3) * 16, nb = t & 7;
        float c[4] = {0.f, 0.f, 0.f, 0.f};
#pragma unroll
        for (int kk = 0; kk < 12; kk++) {
            uint32_t a0 = *(uint32_t*)&dTs[(m3 + g) * 200 + kk * 16 + 2 * tig];
            uint32_t a1 = *(uint32_t*)&dTs[(m3 + g + 8) * 200 + kk * 16 + 2 * tig];
            uint32_t a2 = *(uint32_t*)&dTs[(m3 + g) * 200 + kk * 16 + 2 * tig + 8];
            uint32_t a3 = *(uint32_t*)&dTs[(m3 + g + 8) * 200 + kk * 16 + 2 * tig + 8];
            int k0 = kk * 16 + 2 * tig;
            uint32_t b0 = (uint32_t)*(unsigned short*)&Fs[k0 * 72 + nb * 8 + g]
                        | ((uint32_t)*(unsigned short*)&Fs[(k0 + 1) * 72 + nb * 8 + g] << 16);
            uint32_t b1 = (uint32_t)*(unsigned short*)&Fs[(k0 + 8) * 72 + nb * 8 + g]
                        | ((uint32_t)*(unsigned short*)&Fs[(k0 + 9) * 72 + nb * 8 + g] << 16);
            mma_f16(c, a0, a1, a2, a3, b0, b1);
        }
        int h0 = m3 + g, h1 = h0 + 8, g0 = nb * 8 + 2 * tig;
        float* up = Uout + ((long)n * SEQ + r) * 4096;
        float e0 = sEtot[g0], e1 = sEtot[g0 + 1];
        float ds0 = sdsum[h0], ds1 = sdsum[h1];
        *(float2*)(up + h0 * 64 + g0) =
            make_float2((ds0 * e0 + c[0]) * invZ, (ds0 * e1 + c[1]) * invZ);
        *(float2*)(up + h1 * 64 + g0) =
            make_float2((ds1 * e0 + c[2]) * invZ, (ds1 * e1 + c[3]) * invZ);
    }
}

extern "C" void kernel_launch(void* const* d_in, const int* in_sizes, int n_in,
                              void* d_out, int out_size) {
    const float* x       = (const float*)d_in[0];
    const float* ln_w    = (const float*)d_in[1];
    const float* ln_b    = (const float*)d_in[2];
    const float* W_abcde = (const float*)d_in[3];
    const float* b_abcde = (const float*)d_in[4];
    const float* W_K     = (const float*)d_in[5];
    const float* W_V     = (const float*)d_in[6];
    const float* W_out   = (const float*)d_in[7];
    const float* b_out   = (const float*)d_in[8];
    float* out = (float*)d_out;

    float *xn, *proj, *bsum, *wkr, *step1, *step2, *U, *zb, *Et, *ds;
    uint32_t *pA, *pE, *pdT, *pS2;
    cudaGetSymbolAddress((void**)&xn, g_xn);
    cudaGetSymbolAddress((void**)&proj, g_proj);
    cudaGetSymbolAddress((void**)&bsum, g_bsum);
    cudaGetSymbolAddress((void**)&wkr, g_wkr);
    cudaGetSymbolAddress((void**)&step1, g_step1);
    cudaGetSymbolAddress((void**)&step2, g_step2);
    cudaGetSymbolAddress((void**)&U, g_U);
    cudaGetSymbolAddress((void**)&zb, g_zbuf);
    cudaGetSymbolAddress((void**)&pA, g_pA);
    cudaGetSymbolAddress((void**)&pE, g_pE);
    cudaGetSymbolAddress((void**)&pdT, g_pdT);
    cudaGetSymbolAddress((void**)&pS2, g_pS2);
    cudaGetSymbolAddress((void**)&Et, g_Etot);
    cudaGetSymbolAddress((void**)&ds, g_dsum);

    cudaFuncSetAttribute(attn_mma_kernel, cudaFuncAttributeMaxDynamicSharedMemorySize, 210944);

    ln_kernel<<<SEQ, 256>>>(x, ln_w, ln_b, xn);
    fillb_kernel<<<(SEQ * 2560 + 255) / 256, 256>>>(proj, b_abcde, SEQ * 2560, 2560);
    reshape_wk<<<2048, 256>>>(W_K, wkr);
    gemm_kernel<<<dim3(40, 3, 2), 128>>>(xn, 512, 0, 0, W_abcde, 512, 1, 0, 0,
                                         proj, 2560, 0, 0, 0, 512, 1, 2, 1);
    packn_kernel<<<NH, 256>>>(proj, pA, pE, pdT, Et, ds);
    zero_kernel<<<(SEQ * 4096 + 255) / 256, 256>>>(step1, SEQ * 4096);
    gemm_kernel<<<dim3(64, 3, 2), 128>>>(proj + 1024, 2560, 0, 0, wkr, 512, 1, 0, 0,
                                         step1, 4096, 0, 0, 0, 512, 1, 2, 1);
    bsum_kernel<<<48, 256>>>(proj, bsum);
    gemm_kernel<<<dim3(1, 3, 192), 128>>>(bsum, 64, 0, 0, step1, 64, 1, 4096, 0,
                                          step2, 64, 12288, 0, 0, 64, 192, 1, 0);
    packs2_kernel<<<SEQ, 256>>>(step2, pS2);
    // fused tensor-core attention -> U
    attn_mma_kernel<<<dim3(SEQ, NH), 384, 210944>>>(pA, pE, pdT, pS2, Et, ds, U);
    // z = U @ W_V
    zero_kernel<<<(SEQ * 512 + 255) / 256, 256>>>(zb, SEQ * 512);
    gemm_kernel<<<dim3(1, 3, 64), 128>>>(U, 4096, 786432, 0,
                                         W_V, 1, 64, 262144, 0,
                                         zb, 512, 64, 0, 0, 4096, 8, 8, 1);
    // out = z @ W_out^T + b_out
    fillb_kernel<<<(SEQ * 512 + 255) / 256, 256>>>(out, b_out, SEQ * 512, 512);
    gemm_kernel<<<dim3(8, 3, 4), 128>>>(zb, 512, 0, 0, W_out, 512, 1, 0, 0,
                                        out, 512, 0, 0, 0, 512, 1, 4, 1);
}

// round 17
// speedup vs baseline: 1.8475x; 1.0586x over previous
#include <cuda_runtime.h>
#include <cuda_fp16.h>
#include <cstdint>

#define SEQ 192
#define NH 8

__device__ float g_xn[SEQ * 512];
__device__ float g_proj[SEQ * 2560];
__device__ float g_bsum[SEQ * 64];
__device__ float g_wkr[4096 * 512];
__device__ float g_step1[SEQ * 4096];
__device__ float g_U[NH * SEQ * 4096];
__device__ float g_zbuf[SEQ * 512];
__device__ uint32_t g_pA[NH * 6144];
__device__ uint32_t g_pE[NH * 6144];
__device__ uint32_t g_pdT[NH * 6144];
__device__ uint32_t g_pS2[(long)SEQ * 6144];
__device__ float g_Etot[NH * 64];
__device__ float g_dsum[NH * 64];

typedef unsigned long long u64t;

__device__ __forceinline__ u64t pk2(float lo, float hi) {
    u64t d; asm("mov.b64 %0, {%1, %2};" : "=l"(d) : "f"(lo), "f"(hi)); return d;
}
__device__ __forceinline__ float2 upk2(u64t d) {
    float2 r; asm("mov.b64 {%0, %1}, %2;" : "=f"(r.x), "=f"(r.y) : "l"(d)); return r;
}
__device__ __forceinline__ u64t ffma2(u64t a, u64t b, u64t c) {
    u64t d; asm("fma.rn.f32x2 %0, %1, %2, %3;" : "=l"(d) : "l"(a), "l"(b), "l"(c)); return d;
}
__device__ __forceinline__ uint32_t pkh(float lo, float hi) {
    __half2 h = __floats2half2_rn(lo, hi);
    return *(uint32_t*)&h;
}

__device__ __forceinline__ float fexp(float x) {
    float t = fmaf(x, 1.4426950408889634f, 12582912.0f);
    float kf = t - 12582912.0f;
    int ki = (int)kf;
    float r = fmaf(kf, -0.69314718055994531f, x);
    float p = 1.38888889e-3f;
    p = fmaf(p, r, 8.33333333e-3f);
    p = fmaf(p, r, 4.16666667e-2f);
    p = fmaf(p, r, 1.66666667e-1f);
    p = fmaf(p, r, 0.5f);
    p = fmaf(p, r, 1.0f);
    p = fmaf(p, r, 1.0f);
    return p * __int_as_float((ki + 127) << 23);
}

__device__ __forceinline__ void mma_f16(float c[4], uint32_t a0, uint32_t a1,
                                        uint32_t a2, uint32_t a3,
                                        uint32_t b0, uint32_t b1) {
    asm volatile(
        "mma.sync.aligned.m16n8k16.row.col.f32.f16.f16.f32 "
        "{%0,%1,%2,%3}, {%4,%5,%6,%7}, {%8,%9}, {%0,%1,%2,%3};"
        : "+f"(c[0]), "+f"(c[1]), "+f"(c[2]), "+f"(c[3])
        : "r"(a0), "r"(a1), "r"(a2), "r"(a3), "r"(b0), "r"(b1));
}

// ---------------- LayerNorm ----------------
__global__ __launch_bounds__(256) void ln_kernel(const float* __restrict__ x,
                                                 const float* __restrict__ w,
                                                 const float* __restrict__ b,
                                                 float* __restrict__ xn) {
    __shared__ float rs[256], rq[256];
    int row = blockIdx.x, tid = threadIdx.x;
    float v0 = x[row * 512 + tid], v1 = x[row * 512 + 256 + tid];
    rs[tid] = v0 + v1;
    rq[tid] = v0 * v0 + v1 * v1;
    __syncthreads();
    for (int s = 128; s >= 32; s >>= 1) {
        if (tid < s) { rs[tid] += rs[tid + s]; rq[tid] += rq[tid + s]; }
        __syncthreads();
    }
    if (tid < 32) {
        float a = rs[tid], q = rq[tid];
        for (int o = 16; o; o >>= 1) {
            a += __shfl_down_sync(~0u, a, o);
            q += __shfl_down_sync(~0u, q, o);
        }
        if (!tid) { rs[0] = a; rq[0] = q; }
    }
    __syncthreads();
    float mu = rs[0] * (1.f / 512.f);
    float var = rq[0] * (1.f / 512.f) - mu * mu;
    float is = rsqrtf(var + 1e-5f);
    xn[row * 512 + tid]       = (v0 - mu) * is * w[tid]       + b[tid];
    xn[row * 512 + 256 + tid] = (v1 - mu) * is * w[256 + tid] + b[256 + tid];
}

// ---------------- 64x64 f32x2 GEMM (+ optional packed-half epilogue) -------
__global__ __launch_bounds__(128) void gemm_kernel(
    const float* __restrict__ A, int lda, long sA1, long sA2,
    const float* __restrict__ B, int ldbn, int ldbk, long sB1, long sB2,
    float* __restrict__ C, int ldc, long sC1, long sC2,
    const float* __restrict__ bias,
    int K, int nb1, int kSplits, int doAtomic, int halfOut)
{
    __shared__ float Ast[16][68];
    __shared__ float Bst[16][68];
    int z = blockIdx.z;
    int kz = z % kSplits;
    int t = z / kSplits;
    int b1 = t % nb1, b2 = t / nb1;
    A += b1 * sA1 + b2 * sA2;
    B += b1 * sB1 + b2 * sB2;
    C += b1 * sC1 + b2 * sC2;
    const int kPer = K / kSplits;
    const int k0 = kz * kPer, k1 = k0 + kPer;
    const int m0 = blockIdx.y * 64;
    const int n0 = blockIdx.x * 64;
    const int tid = threadIdx.x;
    const int tn0 = (tid & 15) * 4;
    const int tm0 = (tid >> 4) * 8;
    const int pbn = tid & 63;

    u64t acc[4][4];
#pragma unroll
    for (int i = 0; i < 4; i++)
#pragma unroll
        for (int j = 0; j < 4; j++) acc[i][j] = 0ULL;

    float4 pa[2], pb[2];
    float pbs[8];

#pragma unroll
    for (int j = 0; j < 2; j++) {
        int idx = tid + j * 128;
        pa[j] = *(const float4*)(A + (long)(m0 + (idx >> 2)) * lda + k0 + (idx & 3) * 4);
    }
    if (ldbk == 1) {
#pragma unroll
        for (int j = 0; j < 2; j++) {
            int idx = tid + j * 128;
            pb[j] = *(const float4*)(B + (long)(n0 + (idx >> 2)) * ldbn + k0 + (idx & 3) * 4);
        }
    } else {
#pragma unroll
        for (int j = 0; j < 8; j++) {
            int k = (tid + j * 128) >> 6;
            pbs[j] = B[(long)(k0 + k) * ldbk + (long)(n0 + pbn) * ldbn];
        }
    }

    for (int kk = k0; kk < k1; kk += 16) {
#pragma unroll
        for (int j = 0; j < 2; j++) {
            int idx = tid + j * 128;
            int m = idx >> 2, kq = (idx & 3) * 4;
            Ast[kq + 0][m] = pa[j].x; Ast[kq + 1][m] = pa[j].y;
            Ast[kq + 2][m] = pa[j].z; Ast[kq + 3][m] = pa[j].w;
        }
        if (ldbk == 1) {
#pragma unroll
            for (int j = 0; j < 2; j++) {
                int idx = tid + j * 128;
                int nn = idx >> 2, kq = (idx & 3) * 4;
                Bst[kq + 0][nn] = pb[j].x; Bst[kq + 1][nn] = pb[j].y;
                Bst[kq + 2][nn] = pb[j].z; Bst[kq + 3][nn] = pb[j].w;
            }
        } else {
#pragma unroll
            for (int j = 0; j < 8; j++) {
                int idx = tid + j * 128;
                Bst[idx >> 6][idx & 63] = pbs[j];
            }
        }
        __syncthreads();

        if (kk + 16 < k1) {
            int kn = kk + 16;
#pragma unroll
            for (int j = 0; j < 2; j++) {
                int idx = tid + j * 128;
                pa[j] = *(const float4*)(A + (long)(m0 + (idx >> 2)) * lda + kn + (idx & 3) * 4);
            }
            if (ldbk == 1) {
#pragma unroll
                for (int j = 0; j < 2; j++) {
                    int idx = tid + j * 128;
                    pb[j] = *(const float4*)(B + (long)(n0 + (idx >> 2)) * ldbn + kn + (idx & 3) * 4);
                }
            } else {
#pragma unroll
                for (int j = 0; j < 8; j++) {
                    int k = (tid + j * 128) >> 6;
                    pbs[j] = B[(long)(kn + k) * ldbk + (long)(n0 + pbn) * ldbn];
                }
            }
        }

#pragma unroll
        for (int k = 0; k < 16; k++) {
            ulonglong2 a01 = *(const ulonglong2*)&Ast[k][tm0];
            ulonglong2 a23 = *(const ulonglong2*)&Ast[k][tm0 + 4];
            float4 bv = *(const float4*)&Bst[k][tn0];
            u64t b0 = pk2(bv.x, bv.x), b1p = pk2(bv.y, bv.y);
            u64t b2p = pk2(bv.z, bv.z), b3p = pk2(bv.w, bv.w);
            acc[0][0] = ffma2(a01.x, b0, acc[0][0]);
            acc[0][1] = ffma2(a01.x, b1p, acc[0][1]);
            acc[0][2] = ffma2(a01.x, b2p, acc[0][2]);
            acc[0][3] = ffma2(a01.x, b3p, acc[0][3]);
            acc[1][0] = ffma2(a01.y, b0, acc[1][0]);
            acc[1][1] = ffma2(a01.y, b1p, acc[1][1]);
            acc[1][2] = ffma2(a01.y, b2p, acc[1][2]);
            acc[1][3] = ffma2(a01.y, b3p, acc[1][3]);
            acc[2][0] = ffma2(a23.x, b0, acc[2][0]);
            acc[2][1] = ffma2(a23.x, b1p, acc[2][1]);
            acc[2][2] = ffma2(a23.x, b2p, acc[2][2]);
            acc[2][3] = ffma2(a23.x, b3p, acc[2][3]);
            acc[3][0] = ffma2(a23.y, b0, acc[3][0]);
            acc[3][1] = ffma2(a23.y, b1p, acc[3][1]);
            acc[3][2] = ffma2(a23.y, b2p, acc[3][2]);
            acc[3][3] = ffma2(a23.y, b3p, acc[3][3]);
        }
        __syncthreads();
    }
    if (halfOut) {
        uint32_t* Ch = (uint32_t*)C;
        int ldh = ldc >> 1;
#pragma unroll
        for (int mp = 0; mp < 4; mp++) {
            float2 v0 = upk2(acc[mp][0]), v1 = upk2(acc[mp][1]);
            float2 v2 = upk2(acc[mp][2]), v3 = upk2(acc[mp][3]);
            int m = m0 + tm0 + mp * 2;
            Ch[(long)m * ldh + (tn0 >> 1)]           = pkh(v0.x, v1.x);
            Ch[(long)m * ldh + (tn0 >> 1) + 1]       = pkh(v2.x, v3.x);
            Ch[(long)(m + 1) * ldh + (tn0 >> 1)]     = pkh(v0.y, v1.y);
            Ch[(long)(m + 1) * ldh + (tn0 >> 1) + 1] = pkh(v2.y, v3.y);
        }
        return;
    }
#pragma unroll
    for (int mp = 0; mp < 4; mp++)
#pragma unroll
        for (int j = 0; j < 4; j++) {
            float2 v = upk2(acc[mp][j]);
            int m = m0 + tm0 + mp * 2;
            int nn = n0 + tn0 + j;
            if (doAtomic) {
                atomicAdd(&C[(long)m * ldc + nn], v.x);
                atomicAdd(&C[(long)(m + 1) * ldc + nn], v.y);
            } else {
                float bb = bias ? bias[nn] : 0.f;
                C[(long)m * ldc + nn] = v.x + bb;
                C[(long)(m + 1) * ldc + nn] = v.y + bb;
            }
        }
}

// ---------------- small helpers ----------------
__global__ void bsum_kernel(const float* __restrict__ proj, float* __restrict__ bs) {
    int idx = blockIdx.x * 256 + threadIdx.x;
    if (idx < SEQ * 64) {
        int q = idx >> 6, j = idx & 63;
        float s = 0.f;
#pragma unroll
        for (int nn = 0; nn < 8; nn++) s += proj[q * 2560 + 512 + nn * 64 + j];
        bs[idx] = s;
    }
}

__global__ void reshape_wk(const float* __restrict__ wk, float* __restrict__ out) {
    for (int o = blockIdx.x * blockDim.x + threadIdx.x; o < 4096 * 512;
         o += gridDim.x * blockDim.x) {
        int ij = o >> 9, nk = o & 511;
        int n = nk >> 6, k = nk & 63;
        int i = ij >> 6, j = ij & 63;
        out[o] = wk[n * 262144 + i * 4096 + j * 64 + k];
    }
}

__global__ void zero_kernel(float* p, int n) {
    int i = blockIdx.x * 256 + threadIdx.x;
    if (i < n) p[i] = 0.f;
}

__global__ void fillb_kernel(float* __restrict__ C, const float* __restrict__ bias,
                             int n, int ldm) {
    int i = blockIdx.x * 256 + threadIdx.x;
    if (i < n) C[i] = bias[i % ldm];
}

// pack per-head tensors: A pairs, e pairs, dT pairs, Etot, dsum
__global__ __launch_bounds__(256) void packn_kernel(
    const float* __restrict__ proj, uint32_t* __restrict__ gA,
    uint32_t* __restrict__ geP, uint32_t* __restrict__ gdT,
    float* __restrict__ gEt, float* __restrict__ gds)
{
    int n = blockIdx.x, tid = threadIdx.x;
    for (int idx = tid; idx < 6144; idx += 256) {
        int p = idx >> 5, i2 = idx & 31;
        float2 v = *(const float2*)(proj + p * 2560 + n * 64 + 2 * i2);
        gA[n * 6144 + idx] = pkh(v.x, v.y);
    }
    for (int idx = tid; idx < 6144; idx += 256) {
        int jk = idx >> 6, gg = idx & 63;
        float lo = proj[(2 * jk) * 2560 + 2048 + n * 64 + gg];
        float hi = proj[(2 * jk + 1) * 2560 + 2048 + n * 64 + gg];
        geP[n * 6144 + idx] = pkh(lo, hi);
    }
    for (int idx = tid; idx < 6144; idx += 256) {
        int h = idx / 96, pw = idx - h * 96;
        float lo = proj[(2 * pw) * 2560 + 1536 + n * 64 + h];
        float hi = proj[(2 * pw + 1) * 2560 + 1536 + n * 64 + h];
        gdT[n * 6144 + idx] = pkh(lo, hi);
    }
    if (tid < 64) {
        float s = 0.f, s2 = 0.f;
        for (int q = 0; q < SEQ; q++) {
            s  += proj[q * 2560 + 2048 + n * 64 + tid];
            s2 += proj[q * 2560 + 1536 + n * 64 + tid];
        }
        gEt[n * 64 + tid] = s;
        gds[n * 64 + tid] = s2;
    }
}

// ---------------- fused attention, 12 warps, packed inputs ----------------
// smem: Aa 192x72 half @0 (27648) | S2P 192x36 u32 @27648 (27648)
//       eP 96x72 u32 @55296 (27648) | dTs 64x(100 u32) @82944 (25600)
//       Es 192x200 half @108544 (76800) | Fs 192x72 half @185344 (27648)
__global__ __launch_bounds__(384, 1) void attn_mma_kernel(
    const uint32_t* __restrict__ gA, const uint32_t* __restrict__ geP,
    const uint32_t* __restrict__ gdT, const uint32_t* __restrict__ gS2,
    const float* __restrict__ gEt, const float* __restrict__ gds,
    float* __restrict__ Uout)
{
    extern __shared__ char smem[];
    __half* Aa = (__half*)smem;
    uint32_t* S2P = (uint32_t*)(smem + 27648);
    uint32_t* eP  = (uint32_t*)(smem + 55296);
    __half* dTs = (__half*)(smem + 82944);
    __half* Es  = (__half*)(smem + 108544);
    __half* Fs  = (__half*)(smem + 185344);
    __shared__ float zred[12];
    __shared__ float s_invZ;
    __shared__ float sEtot[64];
    __shared__ float sdsum[64];

    int r = blockIdx.x, n = blockIdx.y, tid = threadIdx.x;
    int wid = tid >> 5, lane = tid & 31;
    int g = lane >> 2, tig = lane & 3;

    if (tid < 64) sEtot[tid] = gEt[n * 64 + tid];
    else if (tid < 128) sdsum[tid - 64] = gds[n * 64 + tid - 64];

    uint32_t* Aa32 = (uint32_t*)Aa;
    uint32_t* dTs32 = (uint32_t*)dTs;
    for (int idx = tid; idx < 6144; idx += 384) {
        int p = idx >> 5, i2 = idx & 31;
        Aa32[p * 36 + i2] = gA[n * 6144 + idx];
    }
    for (int idx = tid; idx < 6144; idx += 384) {
        int jk = idx >> 6, gg = idx & 63;
        eP[jk * 72 + gg] = geP[n * 6144 + idx];
    }
    for (int idx = tid; idx < 6144; idx += 384) {
        int h = idx / 96, pw = idx - h * 96;
        dTs32[h * 100 + pw] = gdT[n * 6144 + idx];
    }
    for (int idx = tid; idx < 6144; idx += 384) {
        int q = idx >> 5, ik = idx & 31;
        S2P[q * 36 + ik] = gS2[(long)r * 6144 + idx];
    }
    __syncthreads();

    // -- GEMM1: warp-private 16-row m-tile; D = masked(exp(S/64)-1) -> Es --
    int m0 = wid * 16;
    uint32_t af[4][4];
#pragma unroll
    for (int kk = 0; kk < 4; kk++) {
        af[kk][0] = *(uint32_t*)&Aa[(m0 + g) * 72 + kk * 16 + 2 * tig];
        af[kk][1] = *(uint32_t*)&Aa[(m0 + g + 8) * 72 + kk * 16 + 2 * tig];
        af[kk][2] = *(uint32_t*)&Aa[(m0 + g) * 72 + kk * 16 + 2 * tig + 8];
        af[kk][3] = *(uint32_t*)&Aa[(m0 + g + 8) * 72 + kk * 16 + 2 * tig + 8];
    }
    float zpart = 0.f;
    for (int nb = 0; nb < 24; nb++) {
        int p0 = m0 + g, p1 = p0 + 8, q0 = nb * 8 + 2 * tig;
        if (nb * 8 + 7 <= m0) {
            // tile fully masked: D == 0, skip MMA + exp
            *(uint32_t*)&Es[p0 * 200 + q0] = 0u;
            *(uint32_t*)&Es[p1 * 200 + q0] = 0u;
            continue;
        }
        float c[4] = {0.f, 0.f, 0.f, 0.f};
#pragma unroll
        for (int kk = 0; kk < 4; kk++) {
            uint32_t b0 = S2P[(nb * 8 + g) * 36 + kk * 8 + tig];
            uint32_t b1 = S2P[(nb * 8 + g) * 36 + kk * 8 + tig + 4];
            mma_f16(c, af[kk][0], af[kk][1], af[kk][2], af[kk][3], b0, b1);
        }
        float d00 = (q0     <= p0) ? 0.0f : fexp(c[0] * 0.015625f) - 1.0f;
        float d01 = (q0 + 1 <= p0) ? 0.0f : fexp(c[1] * 0.015625f) - 1.0f;
        float d10 = (q0     <= p1) ? 0.0f : fexp(c[2] * 0.015625f) - 1.0f;
        float d11 = (q0 + 1 <= p1) ? 0.0f : fexp(c[3] * 0.015625f) - 1.0f;
        zpart += (d00 + d01) + (d10 + d11);
        *(uint32_t*)&Es[p0 * 200 + q0] = pkh(d00, d01);
        *(uint32_t*)&Es[p1 * 200 + q0] = pkh(d10, d11);
    }
    for (int o = 16; o; o >>= 1) zpart += __shfl_down_sync(~0u, zpart, o);
    if (lane == 0) zred[wid] = zpart;

    // -- GEMM2 (warp-private rows, kk-outer): DF = D @ e -> Fs --
    {
        float c2[8][4];
#pragma unroll
        for (int nb = 0; nb < 8; nb++)
#pragma unroll
            for (int j = 0; j < 4; j++) c2[nb][j] = 0.f;
        for (int kk = 0; kk < 12; kk++) {
            uint32_t a0 = *(uint32_t*)&Es[(m0 + g) * 200 + kk * 16 + 2 * tig];
            uint32_t a1 = *(uint32_t*)&Es[(m0 + g + 8) * 200 + kk * 16 + 2 * tig];
            uint32_t a2 = *(uint32_t*)&Es[(m0 + g) * 200 + kk * 16 + 2 * tig + 8];
            uint32_t a3 = *(uint32_t*)&Es[(m0 + g + 8) * 200 + kk * 16 + 2 * tig + 8];
#pragma unroll
            for (int nb = 0; nb < 8; nb++) {
                uint32_t b0 = eP[(kk * 8 + tig) * 72 + nb * 8 + g];
                uint32_t b1 = eP[(kk * 8 + tig + 4) * 72 + nb * 8 + g];
                mma_f16(c2[nb], a0, a1, a2, a3, b0, b1);
            }
        }
#pragma unroll
        for (int nb = 0; nb < 8; nb++) {
            int p0 = m0 + g, p1 = p0 + 8, g0 = nb * 8 + 2 * tig;
            *(uint32_t*)&Fs[p0 * 72 + g0] = pkh(c2[nb][0], c2[nb][1]);
            *(uint32_t*)&Fs[p1 * 72 + g0] = pkh(c2[nb][2], c2[nb][3]);
        }
    }
    __syncthreads();
    if (tid == 0) {
        float zt = 36864.0f;
        for (int w = 0; w < 12; w++) zt += zred[w];
        s_invZ = 1.0f / zt;
    }
    __syncthreads();

    // -- GEMM3: U = dsum*Etot + dTs @ Fs; 32 tiles over 12 warps --
    float invZ = s_invZ;
    for (int t = wid; t < 32; t += 12) {
        int m3 = (t >> 3) * 16, nb = t & 7;
        float c[4] = {0.f, 0.f, 0.f, 0.f};
#pragma unroll
        for (int kk = 0; kk < 12; kk++) {
            uint32_t a0 = *(uint32_t*)&dTs[(m3 + g) * 200 + kk * 16 + 2 * tig];
            uint32_t a1 = *(uint32_t*)&dTs[(m3 + g + 8) * 200 + kk * 16 + 2 * tig];
            uint32_t a2 = *(uint32_t*)&dTs[(m3 + g) * 200 + kk * 16 + 2 * tig + 8];
            uint32_t a3 = *(uint32_t*)&dTs[(m3 + g + 8) * 200 + kk * 16 + 2 * tig + 8];
            int k0 = kk * 16 + 2 * tig;
            uint32_t b0 = (uint32_t)*(unsigned short*)&Fs[k0 * 72 + nb * 8 + g]
                        | ((uint32_t)*(unsigned short*)&Fs[(k0 + 1) * 72 + nb * 8 + g] << 16);
            uint32_t b1 = (uint32_t)*(unsigned short*)&Fs[(k0 + 8) * 72 + nb * 8 + g]
                        | ((uint32_t)*(unsigned short*)&Fs[(k0 + 9) * 72 + nb * 8 + g] << 16);
            mma_f16(c, a0, a1, a2, a3, b0, b1);
        }
        int h0 = m3 + g, h1 = h0 + 8, g0 = nb * 8 + 2 * tig;
        float* up = Uout + ((long)n * SEQ + r) * 4096;
        float e0 = sEtot[g0], e1 = sEtot[g0 + 1];
        float ds0 = sdsum[h0], ds1 = sdsum[h1];
        *(float2*)(up + h0 * 64 + g0) =
            make_float2((ds0 * e0 + c[0]) * invZ, (ds0 * e1 + c[1]) * invZ);
        *(float2*)(up + h1 * 64 + g0) =
            make_float2((ds1 * e0 + c[2]) * invZ, (ds1 * e1 + c[3]) * invZ);
    }
}

extern "C" void kernel_launch(void* const* d_in, const int* in_sizes, int n_in,
                              void* d_out, int out_size) {
    const float* x       = (const float*)d_in[0];
    const float* ln_w    = (const float*)d_in[1];
    const float* ln_b    = (const float*)d_in[2];
    const float* W_abcde = (const float*)d_in[3];
    const float* b_abcde = (const float*)d_in[4];
    const float* W_K     = (const float*)d_in[5];
    const float* W_V     = (const float*)d_in[6];
    const float* W_out   = (const float*)d_in[7];
    const float* b_out   = (const float*)d_in[8];
    float* out = (float*)d_out;

    float *xn, *proj, *bsum, *wkr, *step1, *U, *zb, *Et, *ds;
    uint32_t *pA, *pE, *pdT, *pS2;
    cudaGetSymbolAddress((void**)&xn, g_xn);
    cudaGetSymbolAddress((void**)&proj, g_proj);
    cudaGetSymbolAddress((void**)&bsum, g_bsum);
    cudaGetSymbolAddress((void**)&wkr, g_wkr);
    cudaGetSymbolAddress((void**)&step1, g_step1);
    cudaGetSymbolAddress((void**)&U, g_U);
    cudaGetSymbolAddress((void**)&zb, g_zbuf);
    cudaGetSymbolAddress((void**)&pA, g_pA);
    cudaGetSymbolAddress((void**)&pE, g_pE);
    cudaGetSymbolAddress((void**)&pdT, g_pdT);
    cudaGetSymbolAddress((void**)&pS2, g_pS2);
    cudaGetSymbolAddress((void**)&Et, g_Etot);
    cudaGetSymbolAddress((void**)&ds, g_dsum);

    cudaFuncSetAttribute(attn_mma_kernel, cudaFuncAttributeMaxDynamicSharedMemorySize, 212992);

    ln_kernel<<<SEQ, 256>>>(x, ln_w, ln_b, xn);
    fillb_kernel<<<(SEQ * 2560 + 255) / 256, 256>>>(proj, b_abcde, SEQ * 2560, 2560);
    reshape_wk<<<2048, 256>>>(W_K, wkr);
    gemm_kernel<<<dim3(40, 3, 2), 128>>>(xn, 512, 0, 0, W_abcde, 512, 1, 0, 0,
                                         proj, 2560, 0, 0, 0, 512, 1, 2, 1, 0);
    packn_kernel<<<NH, 256>>>(proj, pA, pE, pdT, Et, ds);
    zero_kernel<<<(SEQ * 4096 + 255) / 256, 256>>>(step1, SEQ * 4096);
    gemm_kernel<<<dim3(64, 3, 2), 128>>>(proj + 1024, 2560, 0, 0, wkr, 512, 1, 0, 0,
                                         step1, 4096, 0, 0, 0, 512, 1, 2, 1, 0);
    bsum_kernel<<<48, 256>>>(proj, bsum);
    // step2: writes packed half pairs [r][q][ik] directly (halfOut)
    gemm_kernel<<<dim3(1, 3, 192), 128>>>(bsum, 64, 0, 0, step1, 64, 1, 4096, 0,
                                          (float*)pS2, 64, 6144, 0, 0, 64, 192, 1, 0, 1);
    // fused tensor-core attention -> U
    attn_mma_kernel<<<dim3(SEQ, NH), 384, 212992>>>(pA, pE, pdT, pS2, Et, ds, U);
    // z = U @ W_V
    zero_kernel<<<(SEQ * 512 + 255) / 256, 256>>>(zb, SEQ * 512);
    gemm_kernel<<<dim3(1, 3, 64), 128>>>(U, 4096, 786432, 0,
                                         W_V, 1, 64, 262144, 0,
                                         zb, 512, 64, 0, 0, 4096, 8, 8, 1, 0);
    // out = z @ W_out^T + b_out
    fillb_kernel<<<(SEQ * 512 + 255) / 256, 256>>>(out, b_out, SEQ * 512, 512);
    gemm_kernel<<<dim3(8, 3, 4), 128>>>(zb, 512, 0, 0, W_out, 512, 1, 0, 0,
                                        out, 512, 0, 0, 0, 512, 1, 4, 1, 0);
}